// round 13
// baseline (speedup 1.0000x reference)
#include <cuda_runtime.h>
#include <cuda_fp16.h>

#define NUQ 100000
#define NIQ 50000
#define NEQ 1000000
#define NTOT (NUQ + NIQ)
#define CSTR 64     // fixed CSR stride (P(deg>=64) ~ 1e-14; writes guarded)
#define WPITCH 72   // halves per smem W row (16B-aligned uint2 stores, conflict-free reads)

// ---------------- scratch (device globals; no allocation allowed) ----------------
__device__ int   g_cnt_u[NUQ];   // fill counters == degrees after k_fill
__device__ int   g_cnt_i[NIQ];
__device__ int   g_col_u[(size_t)NUQ * CSTR];   // per-user neighbor items
__device__ int   g_col_i[(size_t)NIQ * CSTR];   // per-item neighbor users
__device__ float g_su[NUQ], g_iu[NUQ];
__device__ float g_si[NIQ], g_ii[NIQ];
__device__ __half g_xh[(size_t)NTOT * 64];        // current embeddings (fp16)
__device__ __half g_scaled_h[(size_t)NTOT * 64];  // s_r * cur[r] (stage1 gather src)
__device__ __half g_E_h[(size_t)NTOT * 64];       // E (stage2 gather src)
__device__ __half g_acc[(size_t)NTOT * 64];       // running sum for the mean (fp16)
__device__ __half g_gh[(size_t)NTOT * 64];        // g (epi GEMM A operand)
__device__ __half g_Whg[3 * 4096];                // fp16 Wgc per layer
__device__ __half g_Whb[3 * 4096];                // fp16 Wbi per layer

// ---------------- helpers ----------------
__device__ __forceinline__ float lrelu(float x) { return x > 0.f ? x : 0.2f * x; }

__device__ __forceinline__ __half2 h2u(unsigned u) { return *reinterpret_cast<__half2*>(&u); }

__device__ __forceinline__ void acc_h8(float* a, uint4 q) {
    float2 f0 = __half22float2(h2u(q.x));
    float2 f1 = __half22float2(h2u(q.y));
    float2 f2 = __half22float2(h2u(q.z));
    float2 f3 = __half22float2(h2u(q.w));
    a[0] += f0.x; a[1] += f0.y; a[2] += f1.x; a[3] += f1.y;
    a[4] += f2.x; a[5] += f2.y; a[6] += f3.x; a[7] += f3.y;
}
// tree-reduce 4 rows of 8 halves in fp16 (depth 2), flush into fp32 accum
__device__ __forceinline__ void acc_h8x4(float* a, uint4 q0, uint4 q1, uint4 q2, uint4 q3) {
    __half2 sx = __hadd2(__hadd2(h2u(q0.x), h2u(q1.x)), __hadd2(h2u(q2.x), h2u(q3.x)));
    __half2 sy = __hadd2(__hadd2(h2u(q0.y), h2u(q1.y)), __hadd2(h2u(q2.y), h2u(q3.y)));
    __half2 sz = __hadd2(__hadd2(h2u(q0.z), h2u(q1.z)), __hadd2(h2u(q2.z), h2u(q3.z)));
    __half2 sw = __hadd2(__hadd2(h2u(q0.w), h2u(q1.w)), __hadd2(h2u(q2.w), h2u(q3.w)));
    float2 f0 = __half22float2(sx);
    float2 f1 = __half22float2(sy);
    float2 f2 = __half22float2(sz);
    float2 f3 = __half22float2(sw);
    a[0] += f0.x; a[1] += f0.y; a[2] += f1.x; a[3] += f1.y;
    a[4] += f2.x; a[5] += f2.y; a[6] += f3.x; a[7] += f3.y;
}
__device__ __forceinline__ uint4 pack_h8s(const float* a, float sc) {
    uint4 q;
    __half2 h0 = __floats2half2_rn(a[0] * sc, a[1] * sc);
    __half2 h1 = __floats2half2_rn(a[2] * sc, a[3] * sc);
    __half2 h2 = __floats2half2_rn(a[4] * sc, a[5] * sc);
    __half2 h3 = __floats2half2_rn(a[6] * sc, a[7] * sc);
    q.x = *reinterpret_cast<unsigned*>(&h0);
    q.y = *reinterpret_cast<unsigned*>(&h1);
    q.z = *reinterpret_cast<unsigned*>(&h2);
    q.w = *reinterpret_cast<unsigned*>(&h3);
    return q;
}
__device__ __forceinline__ uint2 pack_h4(float x, float y, float z, float w) {
    uint2 q;
    __half2 h0 = __floats2half2_rn(x, y);
    __half2 h1 = __floats2half2_rn(z, w);
    q.x = *reinterpret_cast<unsigned*>(&h0);
    q.y = *reinterpret_cast<unsigned*>(&h1);
    return q;
}
__device__ __forceinline__ void mma16816(float* c, const unsigned* a, const unsigned* b) {
    asm volatile(
        "mma.sync.aligned.m16n8k16.row.col.f32.f16.f16.f32 "
        "{%0,%1,%2,%3}, {%4,%5,%6,%7}, {%8,%9}, {%0,%1,%2,%3};\n"
        : "+f"(c[0]), "+f"(c[1]), "+f"(c[2]), "+f"(c[3])
        : "r"(a[0]), "r"(a[1]), "r"(a[2]), "r"(a[3]), "r"(b[0]), "r"(b[1]));
}

// ---------------- setup kernels ----------------
// zero counters + convert weights to fp16 (merged)
__global__ void k_zero(const float* __restrict__ Wgc, const float* __restrict__ Wbi) {
    int i = blockIdx.x * blockDim.x + threadIdx.x;
    int st = gridDim.x * blockDim.x;
    for (int j = i; j < NUQ; j += st) g_cnt_u[j] = 0;
    for (int j = i; j < NIQ; j += st) g_cnt_i[j] = 0;
    for (int j = i; j < 3 * 4096; j += st) {
        g_Whg[j] = __float2half(Wgc[j]);
        g_Whb[j] = __float2half(Wbi[j]);
    }
}

__global__ void k_fill(const int* __restrict__ eu, const int* __restrict__ ei) {
    int e = blockIdx.x * blockDim.x + threadIdx.x;
    if (e < NEQ) {
        int u = eu[e], it = ei[e];
        int ru = atomicAdd(&g_cnt_u[u], 1);
        if (ru < CSTR) g_col_u[(size_t)u * CSTR + ru] = it;
        int ri = atomicAdd(&g_cnt_i[it], 1);
        if (ri < CSTR) g_col_i[(size_t)it * CSTR + ri] = u;
    }
}

// init fp16 embeddings + scaled copy + degree scalars
__global__ void k_init(const float* __restrict__ ue, const float* __restrict__ ie) {
    int j = blockIdx.x * blockDim.x + threadIdx.x;
    int st = gridDim.x * blockDim.x;
    const int totu = NUQ * 16;
    const int tot = NTOT * 16;
    const float4* u4 = (const float4*)ue;
    const float4* i4 = (const float4*)ie;
    for (; j < tot; j += st) {
        float4 v = (j < totu) ? u4[j] : i4[j - totu];
        int row = j >> 4;
        int d = (row < NUQ) ? g_cnt_u[row] : g_cnt_i[row - NUQ];
        float s = d > 0 ? rsqrtf((float)d) : 0.f;
        if ((j & 15) == 0) {
            float inv = d > 0 ? 1.f / (float)d : 0.f;
            if (row < NUQ) { g_su[row] = s; g_iu[row] = inv; }
            else           { g_si[row - NUQ] = s; g_ii[row - NUQ] = inv; }
        }
        ((uint2*)g_xh)[j] = pack_h4(v.x, v.y, v.z, v.w);
        ((uint2*)g_scaled_h)[j] = pack_h4(v.x * s, v.y * s, v.z * s, v.w * s);
    }
}

// ---------------- graph stages: warp = 4 rows, 8 lanes x LDG.128 per row --------
__global__ __launch_bounds__(256, 6) void k_stage1() {
    int gw = (blockIdx.x * 256 + threadIdx.x) >> 5;
    int lane = threadIdx.x & 31;
    int sub = lane >> 3, l8 = lane & 7;
    int r = gw * 4 + sub;
    if (r >= NTOT) return;

    int deg;
    const int* col;
    const __half* src;
    float sc;
    __half* dst;
    if (r < NIQ) {            // item rows: E_items[i] = ii[i] * sum scaled_users
        deg = min(g_cnt_i[r], CSTR);
        col = g_col_i + (size_t)r * CSTR; src = g_scaled_h;
        sc = g_ii[r]; dst = g_E_h + (size_t)r * 64;
    } else {                  // user rows: E_users[u] = iu[u] * sum scaled_items
        int u = r - NIQ;
        deg = min(g_cnt_u[u], CSTR);
        col = g_col_u + (size_t)u * CSTR; src = g_scaled_h + (size_t)NUQ * 64;
        sc = g_iu[u]; dst = g_E_h + (size_t)(NIQ + u) * 64;
    }

    float a[8] = {0.f, 0.f, 0.f, 0.f, 0.f, 0.f, 0.f, 0.f};
    int nit = deg >> 2;
    if (nit) {
        int4 nn = *(const int4*)(col);
        for (int it = 1; it <= nit; it++) {
            // prefetch next group's indices (predicated) before consuming gathers
            int4 nx = nn;
            if (it < nit) nx = *(const int4*)(col + it * 4);
            uint4 q0 = *(const uint4*)(src + (size_t)nn.x * 64 + l8 * 8);
            uint4 q1 = *(const uint4*)(src + (size_t)nn.y * 64 + l8 * 8);
            uint4 q2 = *(const uint4*)(src + (size_t)nn.z * 64 + l8 * 8);
            uint4 q3 = *(const uint4*)(src + (size_t)nn.w * 64 + l8 * 8);
            acc_h8x4(a, q0, q1, q2, q3);
            nn = nx;
        }
    }
    for (int e = nit * 4; e < deg; e++) {
        int n = col[e];
        uint4 q = *(const uint4*)(src + (size_t)n * 64 + l8 * 8);
        acc_h8(a, q);
    }
    *(uint4*)(dst + l8 * 8) = pack_h8s(a, sc);
}

__global__ __launch_bounds__(256, 6) void k_stage2() {
    int gw = (blockIdx.x * 256 + threadIdx.x) >> 5;
    int lane = threadIdx.x & 31;
    int sub = lane >> 3, l8 = lane & 7;
    int r = gw * 4 + sub;
    if (r >= NTOT) return;

    int deg;
    const int* col;
    const __half* src;
    float sc;
    if (r < NUQ) {            // user rows: g_u = su[u] * sum E_items[neighbors]
        deg = min(g_cnt_u[r], CSTR);
        col = g_col_u + (size_t)r * CSTR; src = g_E_h; sc = g_su[r];
    } else {                  // item rows: g_i = si[i] * sum E_users[neighbors]
        int i = r - NUQ;
        deg = min(g_cnt_i[i], CSTR);
        col = g_col_i + (size_t)i * CSTR; src = g_E_h + (size_t)NIQ * 64; sc = g_si[i];
    }

    float a[8] = {0.f, 0.f, 0.f, 0.f, 0.f, 0.f, 0.f, 0.f};
    int nit = deg >> 2;
    if (nit) {
        int4 nn = *(const int4*)(col);
        for (int it = 1; it <= nit; it++) {
            int4 nx = nn;
            if (it < nit) nx = *(const int4*)(col + it * 4);
            uint4 q0 = *(const uint4*)(src + (size_t)nn.x * 64 + l8 * 8);
            uint4 q1 = *(const uint4*)(src + (size_t)nn.y * 64 + l8 * 8);
            uint4 q2 = *(const uint4*)(src + (size_t)nn.z * 64 + l8 * 8);
            uint4 q3 = *(const uint4*)(src + (size_t)nn.w * 64 + l8 * 8);
            acc_h8x4(a, q0, q1, q2, q3);
            nn = nx;
        }
    }
    for (int e = nit * 4; e < deg; e++) {
        int n = col[e];
        uint4 q = *(const uint4*)(src + (size_t)n * 64 + l8 * 8);
        acc_h8(a, q);
    }
    *(uint4*)(g_gh + (size_t)r * 64 + l8 * 8) = pack_h8s(a, sc);
}

// ---------------- epilogue: tensor-core dual GEMM (p-frags via hmul2) ----------------
__global__ __launch_bounds__(128) void k_epi(const __half* __restrict__ Whg,
                                             const float* __restrict__ bgc,
                                             const __half* __restrict__ Whb,
                                             const float* __restrict__ bbi,
                                             float* __restrict__ out,
                                             int first, int last) {
    __shared__ __half sWg[64 * WPITCH];
    __shared__ __half sWb[64 * WPITCH];
    __shared__ float sbg[64], sbb[64];
    for (int i = threadIdx.x; i < 1024; i += 128) {
        int d = i >> 4, k4 = (i & 15) * 4;
        *(uint2*)&sWg[d * WPITCH + k4] = ((const uint2*)Whg)[i];
        *(uint2*)&sWb[d * WPITCH + k4] = ((const uint2*)Whb)[i];
    }
    if (threadIdx.x < 64) { sbg[threadIdx.x] = bgc[threadIdx.x]; sbb[threadIdx.x] = bbi[threadIdx.x]; }
    __syncthreads();

    int lane = threadIdx.x & 31;
    int gw = (blockIdx.x * 128 + threadIdx.x) >> 5;
    int nw = gridDim.x * 4;
    int qr = lane >> 2;          // 0..7
    int qc = (lane & 3) * 2;     // 0,2,4,6

    const int ntiles = NTOT / 16;   // 9375
    for (int t0 = gw; t0 < ntiles; t0 += nw) {
        int r0 = t0 * 16;
        int R0 = r0 + qr, R1 = R0 + 8;
        float cg[8][4], cp[8][4];
#pragma unroll
        for (int j = 0; j < 8; j++) {
#pragma unroll
            for (int q = 0; q < 4; q++) { cg[j][q] = 0.f; cp[j][q] = 0.f; }
        }
        // fused dual GEMM: D_g = g @ Wgc^T,  D_p = (g.*x) @ Wbi^T
#pragma unroll
        for (int t = 0; t < 4; t++) {
            int k0 = 16 * t + qc;
            unsigned ag[4], ax[4], ap[4];
            ag[0] = *(const unsigned*)(g_gh + (size_t)R0 * 64 + k0);
            ag[1] = *(const unsigned*)(g_gh + (size_t)R1 * 64 + k0);
            ag[2] = *(const unsigned*)(g_gh + (size_t)R0 * 64 + k0 + 8);
            ag[3] = *(const unsigned*)(g_gh + (size_t)R1 * 64 + k0 + 8);
            ax[0] = *(const unsigned*)(g_xh + (size_t)R0 * 64 + k0);
            ax[1] = *(const unsigned*)(g_xh + (size_t)R1 * 64 + k0);
            ax[2] = *(const unsigned*)(g_xh + (size_t)R0 * 64 + k0 + 8);
            ax[3] = *(const unsigned*)(g_xh + (size_t)R1 * 64 + k0 + 8);
#pragma unroll
            for (int q = 0; q < 4; q++) {
                __half2 hp = __hmul2(h2u(ag[q]), h2u(ax[q]));
                ap[q] = *reinterpret_cast<unsigned*>(&hp);
            }
#pragma unroll
            for (int j = 0; j < 8; j++) {
                const __half* wpg = &sWg[(8 * j + qr) * WPITCH + 16 * t + qc];
                const __half* wpb = &sWb[(8 * j + qr) * WPITCH + 16 * t + qc];
                unsigned bg[2], bb[2];
                bg[0] = *(const unsigned*)(wpg);
                bg[1] = *(const unsigned*)(wpg + 8);
                bb[0] = *(const unsigned*)(wpb);
                bb[1] = *(const unsigned*)(wpb + 8);
                mma16816(cg[j], ag, bg);
                mma16816(cp[j], ap, bb);
            }
        }
        // epilogue: y = lrelu(gc + bgc + x) + lrelu(bi + bbi); row-normalize; mean-acc
        float ssA = 0.f, ssB = 0.f;
#pragma unroll
        for (int j = 0; j < 8; j++) {
            int d0 = 8 * j + qc;
            float2 xA = __half22float2(*(const __half2*)(g_xh + (size_t)R0 * 64 + d0));
            float2 xB = __half22float2(*(const __half2*)(g_xh + (size_t)R1 * 64 + d0));
            float bg0 = sbg[d0], bg1 = sbg[d0 + 1];
            float bb0 = sbb[d0], bb1 = sbb[d0 + 1];
            float yA0 = lrelu(cg[j][0] + bg0 + xA.x) + lrelu(cp[j][0] + bb0);
            float yA1 = lrelu(cg[j][1] + bg1 + xA.y) + lrelu(cp[j][1] + bb1);
            float yB0 = lrelu(cg[j][2] + bg0 + xB.x) + lrelu(cp[j][2] + bb0);
            float yB1 = lrelu(cg[j][3] + bg1 + xB.y) + lrelu(cp[j][3] + bb1);
            cg[j][0] = yA0; cg[j][1] = yA1; cg[j][2] = yB0; cg[j][3] = yB1;
            // stash x in the now-dead cp fragments (used when first==1: acc==x)
            cp[j][0] = xA.x; cp[j][1] = xA.y; cp[j][2] = xB.x; cp[j][3] = xB.y;
            ssA += yA0 * yA0 + yA1 * yA1;
            ssB += yB0 * yB0 + yB1 * yB1;
        }
        ssA += __shfl_xor_sync(0xffffffffu, ssA, 1);
        ssA += __shfl_xor_sync(0xffffffffu, ssA, 2);
        ssB += __shfl_xor_sync(0xffffffffu, ssB, 1);
        ssB += __shfl_xor_sync(0xffffffffu, ssB, 2);
        float scA = 1.0f / fmaxf(sqrtf(ssA), 1e-12f);
        float scB = 1.0f / fmaxf(sqrtf(ssB), 1e-12f);
        float sA = 0.f, sB = 0.f;
        if (!last) {
            sA = (R0 < NUQ) ? g_su[R0] : g_si[R0 - NUQ];
            sB = (R1 < NUQ) ? g_su[R1] : g_si[R1 - NUQ];
        }
#pragma unroll
        for (int j = 0; j < 8; j++) {
            int d0 = 8 * j + qc;
            float yA0 = cg[j][0] * scA, yA1 = cg[j][1] * scA;
            float yB0 = cg[j][2] * scB, yB1 = cg[j][3] * scB;
            float2 aA, aB;
            if (first) {
                aA = make_float2(cp[j][0], cp[j][1]);
                aB = make_float2(cp[j][2], cp[j][3]);
            } else {
                aA = __half22float2(*(const __half2*)(g_acc + (size_t)R0 * 64 + d0));
                aB = __half22float2(*(const __half2*)(g_acc + (size_t)R1 * 64 + d0));
            }
            if (last) {
                *(float2*)(out + (size_t)R0 * 64 + d0) =
                    make_float2((aA.x + yA0) * 0.25f, (aA.y + yA1) * 0.25f);
                *(float2*)(out + (size_t)R1 * 64 + d0) =
                    make_float2((aB.x + yB0) * 0.25f, (aB.y + yB1) * 0.25f);
            } else {
                *(__half2*)(g_xh + (size_t)R0 * 64 + d0) = __floats2half2_rn(yA0, yA1);
                *(__half2*)(g_xh + (size_t)R1 * 64 + d0) = __floats2half2_rn(yB0, yB1);
                *(__half2*)(g_acc + (size_t)R0 * 64 + d0) = __floats2half2_rn(aA.x + yA0, aA.y + yA1);
                *(__half2*)(g_acc + (size_t)R1 * 64 + d0) = __floats2half2_rn(aB.x + yB0, aB.y + yB1);
                *(__half2*)(g_scaled_h + (size_t)R0 * 64 + d0) = __floats2half2_rn(yA0 * sA, yA1 * sA);
                *(__half2*)(g_scaled_h + (size_t)R1 * 64 + d0) = __floats2half2_rn(yB0 * sB, yB1 * sB);
            }
        }
    }
}

// ---------------- launch ----------------
extern "C" void kernel_launch(void* const* d_in, const int* in_sizes, int n_in,
                              void* d_out, int out_size) {
    const float* ue  = (const float*)d_in[0];
    const float* ie  = (const float*)d_in[1];
    const float* Wgc = (const float*)d_in[2];
    const float* bgc = (const float*)d_in[3];
    const float* Wbi = (const float*)d_in[4];
    const float* bbi = (const float*)d_in[5];
    const int*   eu  = (const int*)d_in[6];
    const int*   ei  = (const int*)d_in[7];
    float* out = (float*)d_out;

    const int stage_blocks = (NTOT / 4 + 7) / 8;   // 4 rows/warp, 8 warps/block
    const int epi_blocks = (NTOT / 16 + 3) / 4;    // 1 tile per warp, 4 warps/block

    k_zero<<<256, 256>>>(Wgc, Wbi);
    k_fill<<<(NEQ + 255) / 256, 256>>>(eu, ei);
    k_init<<<4096, 256>>>(ue, ie);

    static __half* whg_dev = nullptr;
    static __half* whb_dev = nullptr;
    if (!whg_dev) {
        cudaGetSymbolAddress((void**)&whg_dev, g_Whg);
        cudaGetSymbolAddress((void**)&whb_dev, g_Whb);
    }

    for (int l = 0; l < 3; l++) {
        k_stage1<<<stage_blocks, 256>>>();
        k_stage2<<<stage_blocks, 256>>>();
        k_epi<<<epi_blocks, 128>>>(whg_dev + l * 4096, bgc + l * 64,
                                   whb_dev + l * 4096, bbi + l * 64,
                                   out, l == 0 ? 1 : 0, l == 2 ? 1 : 0);
    }
}

// round 14
// speedup vs baseline: 1.0625x; 1.0625x over previous
#include <cuda_runtime.h>
#include <cuda_fp16.h>

#define NUQ 100000
#define NIQ 50000
#define NEQ 1000000
#define NTOT (NUQ + NIQ)
#define CSTR 64     // fixed CSR stride (P(deg>=64) ~ 1e-14; writes guarded)
#define WPITCH 72   // halves per smem W row (16B-aligned uint2 stores, conflict-free reads)

// ---------------- scratch (device globals; no allocation allowed) ----------------
__device__ int   g_cnt_u[NUQ];   // fill counters == degrees after k_fill
__device__ int   g_cnt_i[NIQ];
__device__ int   g_col_u[(size_t)NUQ * CSTR];   // per-user neighbor items
__device__ int   g_col_i[(size_t)NIQ * CSTR];   // per-item neighbor users
__device__ float g_su[NUQ], g_iu[NUQ];
__device__ float g_si[NIQ], g_ii[NIQ];
__device__ __half g_xh[(size_t)NTOT * 64];        // current embeddings (fp16)
__device__ __half g_scaled_h[(size_t)NTOT * 64];  // s_r * cur[r] (stage1 gather src)
__device__ __half g_E_h[(size_t)NTOT * 64];       // E (stage2 gather src)
__device__ __half g_acc[(size_t)NTOT * 64];       // running sum for the mean (fp16)
__device__ __half g_gh[(size_t)NTOT * 64];        // g (epi GEMM A operand)
__device__ __half g_Whg[3 * 4096];                // fp16 Wgc per layer
__device__ __half g_Whb[3 * 4096];                // fp16 Wbi per layer

// ---------------- helpers ----------------
__device__ __forceinline__ float lrelu(float x) { return x > 0.f ? x : 0.2f * x; }

__device__ __forceinline__ __half2 h2u(unsigned u) { return *reinterpret_cast<__half2*>(&u); }

__device__ __forceinline__ void acc_h8(float* a, uint4 q) {
    float2 f0 = __half22float2(h2u(q.x));
    float2 f1 = __half22float2(h2u(q.y));
    float2 f2 = __half22float2(h2u(q.z));
    float2 f3 = __half22float2(h2u(q.w));
    a[0] += f0.x; a[1] += f0.y; a[2] += f1.x; a[3] += f1.y;
    a[4] += f2.x; a[5] += f2.y; a[6] += f3.x; a[7] += f3.y;
}
// tree-reduce 4 rows of 8 halves in fp16 (depth 2), flush into fp32 accum
__device__ __forceinline__ void acc_h8x4(float* a, uint4 q0, uint4 q1, uint4 q2, uint4 q3) {
    __half2 sx = __hadd2(__hadd2(h2u(q0.x), h2u(q1.x)), __hadd2(h2u(q2.x), h2u(q3.x)));
    __half2 sy = __hadd2(__hadd2(h2u(q0.y), h2u(q1.y)), __hadd2(h2u(q2.y), h2u(q3.y)));
    __half2 sz = __hadd2(__hadd2(h2u(q0.z), h2u(q1.z)), __hadd2(h2u(q2.z), h2u(q3.z)));
    __half2 sw = __hadd2(__hadd2(h2u(q0.w), h2u(q1.w)), __hadd2(h2u(q2.w), h2u(q3.w)));
    float2 f0 = __half22float2(sx);
    float2 f1 = __half22float2(sy);
    float2 f2 = __half22float2(sz);
    float2 f3 = __half22float2(sw);
    a[0] += f0.x; a[1] += f0.y; a[2] += f1.x; a[3] += f1.y;
    a[4] += f2.x; a[5] += f2.y; a[6] += f3.x; a[7] += f3.y;
}
__device__ __forceinline__ uint4 pack_h8s(const float* a, float sc) {
    uint4 q;
    __half2 h0 = __floats2half2_rn(a[0] * sc, a[1] * sc);
    __half2 h1 = __floats2half2_rn(a[2] * sc, a[3] * sc);
    __half2 h2 = __floats2half2_rn(a[4] * sc, a[5] * sc);
    __half2 h3 = __floats2half2_rn(a[6] * sc, a[7] * sc);
    q.x = *reinterpret_cast<unsigned*>(&h0);
    q.y = *reinterpret_cast<unsigned*>(&h1);
    q.z = *reinterpret_cast<unsigned*>(&h2);
    q.w = *reinterpret_cast<unsigned*>(&h3);
    return q;
}
__device__ __forceinline__ uint2 pack_h4(float x, float y, float z, float w) {
    uint2 q;
    __half2 h0 = __floats2half2_rn(x, y);
    __half2 h1 = __floats2half2_rn(z, w);
    q.x = *reinterpret_cast<unsigned*>(&h0);
    q.y = *reinterpret_cast<unsigned*>(&h1);
    return q;
}
__device__ __forceinline__ void mma16816(float* c, const unsigned* a, const unsigned* b) {
    asm volatile(
        "mma.sync.aligned.m16n8k16.row.col.f32.f16.f16.f32 "
        "{%0,%1,%2,%3}, {%4,%5,%6,%7}, {%8,%9}, {%0,%1,%2,%3};\n"
        : "+f"(c[0]), "+f"(c[1]), "+f"(c[2]), "+f"(c[3])
        : "r"(a[0]), "r"(a[1]), "r"(a[2]), "r"(a[3]), "r"(b[0]), "r"(b[1]));
}

// ---------------- setup kernels ----------------
// zero counters + convert weights to fp16 (merged)
__global__ void k_zero(const float* __restrict__ Wgc, const float* __restrict__ Wbi) {
    int i = blockIdx.x * blockDim.x + threadIdx.x;
    int st = gridDim.x * blockDim.x;
    for (int j = i; j < NUQ; j += st) g_cnt_u[j] = 0;
    for (int j = i; j < NIQ; j += st) g_cnt_i[j] = 0;
    for (int j = i; j < 3 * 4096; j += st) {
        g_Whg[j] = __float2half(Wgc[j]);
        g_Whb[j] = __float2half(Wbi[j]);
    }
}

__global__ void k_fill(const int* __restrict__ eu, const int* __restrict__ ei) {
    int e = blockIdx.x * blockDim.x + threadIdx.x;
    if (e < NEQ) {
        int u = eu[e], it = ei[e];
        int ru = atomicAdd(&g_cnt_u[u], 1);
        if (ru < CSTR) g_col_u[(size_t)u * CSTR + ru] = it;
        int ri = atomicAdd(&g_cnt_i[it], 1);
        if (ri < CSTR) g_col_i[(size_t)it * CSTR + ri] = u;
    }
}

// init fp16 embeddings + scaled copy + degree scalars
__global__ void k_init(const float* __restrict__ ue, const float* __restrict__ ie) {
    int j = blockIdx.x * blockDim.x + threadIdx.x;
    int st = gridDim.x * blockDim.x;
    const int totu = NUQ * 16;
    const int tot = NTOT * 16;
    const float4* u4 = (const float4*)ue;
    const float4* i4 = (const float4*)ie;
    for (; j < tot; j += st) {
        float4 v = (j < totu) ? u4[j] : i4[j - totu];
        int row = j >> 4;
        int d = (row < NUQ) ? g_cnt_u[row] : g_cnt_i[row - NUQ];
        float s = d > 0 ? rsqrtf((float)d) : 0.f;
        if ((j & 15) == 0) {
            float inv = d > 0 ? 1.f / (float)d : 0.f;
            if (row < NUQ) { g_su[row] = s; g_iu[row] = inv; }
            else           { g_si[row - NUQ] = s; g_ii[row - NUQ] = inv; }
        }
        ((uint2*)g_xh)[j] = pack_h4(v.x, v.y, v.z, v.w);
        ((uint2*)g_scaled_h)[j] = pack_h4(v.x * s, v.y * s, v.z * s, v.w * s);
    }
}

// ---------------- graph stages: warp = 4 rows, 8 lanes x LDG.128 per row --------
__global__ __launch_bounds__(256, 6) void k_stage1() {
    int gw = (blockIdx.x * 256 + threadIdx.x) >> 5;
    int lane = threadIdx.x & 31;
    int sub = lane >> 3, l8 = lane & 7;
    int r = gw * 4 + sub;
    if (r >= NTOT) return;

    int deg;
    const int* col;
    const __half* src;
    float sc;
    __half* dst;
    if (r < NIQ) {            // item rows: E_items[i] = ii[i] * sum scaled_users
        deg = min(g_cnt_i[r], CSTR);
        col = g_col_i + (size_t)r * CSTR; src = g_scaled_h;
        sc = g_ii[r]; dst = g_E_h + (size_t)r * 64;
    } else {                  // user rows: E_users[u] = iu[u] * sum scaled_items
        int u = r - NIQ;
        deg = min(g_cnt_u[u], CSTR);
        col = g_col_u + (size_t)u * CSTR; src = g_scaled_h + (size_t)NUQ * 64;
        sc = g_iu[u]; dst = g_E_h + (size_t)(NIQ + u) * 64;
    }

    float a[8] = {0.f, 0.f, 0.f, 0.f, 0.f, 0.f, 0.f, 0.f};
    int e = 0;
    for (; e + 4 <= deg; e += 4) {
        int4 nn = *(const int4*)(col + e);   // 16B-aligned (CSTR%4==0, e%4==0)
        uint4 q0 = *(const uint4*)(src + (size_t)nn.x * 64 + l8 * 8);
        uint4 q1 = *(const uint4*)(src + (size_t)nn.y * 64 + l8 * 8);
        uint4 q2 = *(const uint4*)(src + (size_t)nn.z * 64 + l8 * 8);
        uint4 q3 = *(const uint4*)(src + (size_t)nn.w * 64 + l8 * 8);
        acc_h8x4(a, q0, q1, q2, q3);
    }
    for (; e < deg; e++) {
        int n = col[e];
        uint4 q = *(const uint4*)(src + (size_t)n * 64 + l8 * 8);
        acc_h8(a, q);
    }
    *(uint4*)(dst + l8 * 8) = pack_h8s(a, sc);
}

__global__ __launch_bounds__(256, 6) void k_stage2() {
    int gw = (blockIdx.x * 256 + threadIdx.x) >> 5;
    int lane = threadIdx.x & 31;
    int sub = lane >> 3, l8 = lane & 7;
    int r = gw * 4 + sub;
    if (r >= NTOT) return;

    int deg;
    const int* col;
    const __half* src;
    float sc;
    if (r < NUQ) {            // user rows: g_u = su[u] * sum E_items[neighbors]
        deg = min(g_cnt_u[r], CSTR);
        col = g_col_u + (size_t)r * CSTR; src = g_E_h; sc = g_su[r];
    } else {                  // item rows: g_i = si[i] * sum E_users[neighbors]
        int i = r - NUQ;
        deg = min(g_cnt_i[i], CSTR);
        col = g_col_i + (size_t)i * CSTR; src = g_E_h + (size_t)NIQ * 64; sc = g_si[i];
    }

    float a[8] = {0.f, 0.f, 0.f, 0.f, 0.f, 0.f, 0.f, 0.f};
    int e = 0;
    for (; e + 4 <= deg; e += 4) {
        int4 nn = *(const int4*)(col + e);
        uint4 q0 = *(const uint4*)(src + (size_t)nn.x * 64 + l8 * 8);
        uint4 q1 = *(const uint4*)(src + (size_t)nn.y * 64 + l8 * 8);
        uint4 q2 = *(const uint4*)(src + (size_t)nn.z * 64 + l8 * 8);
        uint4 q3 = *(const uint4*)(src + (size_t)nn.w * 64 + l8 * 8);
        acc_h8x4(a, q0, q1, q2, q3);
    }
    for (; e < deg; e++) {
        int n = col[e];
        uint4 q = *(const uint4*)(src + (size_t)n * 64 + l8 * 8);
        acc_h8(a, q);
    }
    *(uint4*)(g_gh + (size_t)r * 64 + l8 * 8) = pack_h8s(a, sc);
}

// ---------------- epilogue: tensor-core dual GEMM (p-frags via hmul2) ----------------
__global__ __launch_bounds__(128) void k_epi(const __half* __restrict__ Whg,
                                             const float* __restrict__ bgc,
                                             const __half* __restrict__ Whb,
                                             const float* __restrict__ bbi,
                                             float* __restrict__ out,
                                             int first, int last) {
    __shared__ __half sWg[64 * WPITCH];
    __shared__ __half sWb[64 * WPITCH];
    __shared__ float sbg[64], sbb[64];
    for (int i = threadIdx.x; i < 1024; i += 128) {
        int d = i >> 4, k4 = (i & 15) * 4;
        *(uint2*)&sWg[d * WPITCH + k4] = ((const uint2*)Whg)[i];
        *(uint2*)&sWb[d * WPITCH + k4] = ((const uint2*)Whb)[i];
    }
    if (threadIdx.x < 64) { sbg[threadIdx.x] = bgc[threadIdx.x]; sbb[threadIdx.x] = bbi[threadIdx.x]; }
    __syncthreads();

    int lane = threadIdx.x & 31;
    int gw = (blockIdx.x * 128 + threadIdx.x) >> 5;
    int nw = gridDim.x * 4;
    int qr = lane >> 2;          // 0..7
    int qc = (lane & 3) * 2;     // 0,2,4,6

    const int ntiles = NTOT / 16;   // 9375
    for (int t0 = gw; t0 < ntiles; t0 += nw) {
        int r0 = t0 * 16;
        int R0 = r0 + qr, R1 = R0 + 8;
        float cg[8][4], cp[8][4];
#pragma unroll
        for (int j = 0; j < 8; j++) {
#pragma unroll
            for (int q = 0; q < 4; q++) { cg[j][q] = 0.f; cp[j][q] = 0.f; }
        }
        // fused dual GEMM: D_g = g @ Wgc^T,  D_p = (g.*x) @ Wbi^T
#pragma unroll
        for (int t = 0; t < 4; t++) {
            int k0 = 16 * t + qc;
            unsigned ag[4], ax[4], ap[4];
            ag[0] = *(const unsigned*)(g_gh + (size_t)R0 * 64 + k0);
            ag[1] = *(const unsigned*)(g_gh + (size_t)R1 * 64 + k0);
            ag[2] = *(const unsigned*)(g_gh + (size_t)R0 * 64 + k0 + 8);
            ag[3] = *(const unsigned*)(g_gh + (size_t)R1 * 64 + k0 + 8);
            ax[0] = *(const unsigned*)(g_xh + (size_t)R0 * 64 + k0);
            ax[1] = *(const unsigned*)(g_xh + (size_t)R1 * 64 + k0);
            ax[2] = *(const unsigned*)(g_xh + (size_t)R0 * 64 + k0 + 8);
            ax[3] = *(const unsigned*)(g_xh + (size_t)R1 * 64 + k0 + 8);
#pragma unroll
            for (int q = 0; q < 4; q++) {
                __half2 hp = __hmul2(h2u(ag[q]), h2u(ax[q]));
                ap[q] = *reinterpret_cast<unsigned*>(&hp);
            }
#pragma unroll
            for (int j = 0; j < 8; j++) {
                const __half* wpg = &sWg[(8 * j + qr) * WPITCH + 16 * t + qc];
                const __half* wpb = &sWb[(8 * j + qr) * WPITCH + 16 * t + qc];
                unsigned bg[2], bb[2];
                bg[0] = *(const unsigned*)(wpg);
                bg[1] = *(const unsigned*)(wpg + 8);
                bb[0] = *(const unsigned*)(wpb);
                bb[1] = *(const unsigned*)(wpb + 8);
                mma16816(cg[j], ag, bg);
                mma16816(cp[j], ap, bb);
            }
        }
        // epilogue: y = lrelu(gc + bgc + x) + lrelu(bi + bbi); row-normalize; mean-acc
        float ssA = 0.f, ssB = 0.f;
#pragma unroll
        for (int j = 0; j < 8; j++) {
            int d0 = 8 * j + qc;
            float2 xA = __half22float2(*(const __half2*)(g_xh + (size_t)R0 * 64 + d0));
            float2 xB = __half22float2(*(const __half2*)(g_xh + (size_t)R1 * 64 + d0));
            float bg0 = sbg[d0], bg1 = sbg[d0 + 1];
            float bb0 = sbb[d0], bb1 = sbb[d0 + 1];
            float yA0 = lrelu(cg[j][0] + bg0 + xA.x) + lrelu(cp[j][0] + bb0);
            float yA1 = lrelu(cg[j][1] + bg1 + xA.y) + lrelu(cp[j][1] + bb1);
            float yB0 = lrelu(cg[j][2] + bg0 + xB.x) + lrelu(cp[j][2] + bb0);
            float yB1 = lrelu(cg[j][3] + bg1 + xB.y) + lrelu(cp[j][3] + bb1);
            cg[j][0] = yA0; cg[j][1] = yA1; cg[j][2] = yB0; cg[j][3] = yB1;
            // stash x in the now-dead cp fragments (used when first==1: acc==x)
            cp[j][0] = xA.x; cp[j][1] = xA.y; cp[j][2] = xB.x; cp[j][3] = xB.y;
            ssA += yA0 * yA0 + yA1 * yA1;
            ssB += yB0 * yB0 + yB1 * yB1;
        }
        ssA += __shfl_xor_sync(0xffffffffu, ssA, 1);
        ssA += __shfl_xor_sync(0xffffffffu, ssA, 2);
        ssB += __shfl_xor_sync(0xffffffffu, ssB, 1);
        ssB += __shfl_xor_sync(0xffffffffu, ssB, 2);
        float scA = 1.0f / fmaxf(sqrtf(ssA), 1e-12f);
        float scB = 1.0f / fmaxf(sqrtf(ssB), 1e-12f);
        float sA = 0.f, sB = 0.f;
        if (!last) {
            sA = (R0 < NUQ) ? g_su[R0] : g_si[R0 - NUQ];
            sB = (R1 < NUQ) ? g_su[R1] : g_si[R1 - NUQ];
        }
#pragma unroll
        for (int j = 0; j < 8; j++) {
            int d0 = 8 * j + qc;
            float yA0 = cg[j][0] * scA, yA1 = cg[j][1] * scA;
            float yB0 = cg[j][2] * scB, yB1 = cg[j][3] * scB;
            float2 aA, aB;
            if (first) {
                aA = make_float2(cp[j][0], cp[j][1]);
                aB = make_float2(cp[j][2], cp[j][3]);
            } else {
                aA = __half22float2(*(const __half2*)(g_acc + (size_t)R0 * 64 + d0));
                aB = __half22float2(*(const __half2*)(g_acc + (size_t)R1 * 64 + d0));
            }
            if (last) {
                *(float2*)(out + (size_t)R0 * 64 + d0) =
                    make_float2((aA.x + yA0) * 0.25f, (aA.y + yA1) * 0.25f);
                *(float2*)(out + (size_t)R1 * 64 + d0) =
                    make_float2((aB.x + yB0) * 0.25f, (aB.y + yB1) * 0.25f);
            } else {
                *(__half2*)(g_xh + (size_t)R0 * 64 + d0) = __floats2half2_rn(yA0, yA1);
                *(__half2*)(g_xh + (size_t)R1 * 64 + d0) = __floats2half2_rn(yB0, yB1);
                *(__half2*)(g_acc + (size_t)R0 * 64 + d0) = __floats2half2_rn(aA.x + yA0, aA.y + yA1);
                *(__half2*)(g_acc + (size_t)R1 * 64 + d0) = __floats2half2_rn(aB.x + yB0, aB.y + yB1);
                *(__half2*)(g_scaled_h + (size_t)R0 * 64 + d0) = __floats2half2_rn(yA0 * sA, yA1 * sA);
                *(__half2*)(g_scaled_h + (size_t)R1 * 64 + d0) = __floats2half2_rn(yB0 * sB, yB1 * sB);
            }
        }
    }
}

// ---------------- launch ----------------
extern "C" void kernel_launch(void* const* d_in, const int* in_sizes, int n_in,
                              void* d_out, int out_size) {
    const float* ue  = (const float*)d_in[0];
    const float* ie  = (const float*)d_in[1];
    const float* Wgc = (const float*)d_in[2];
    const float* bgc = (const float*)d_in[3];
    const float* Wbi = (const float*)d_in[4];
    const float* bbi = (const float*)d_in[5];
    const int*   eu  = (const int*)d_in[6];
    const int*   ei  = (const int*)d_in[7];
    float* out = (float*)d_out;

    const int stage_blocks = (NTOT / 4 + 7) / 8;   // 4 rows/warp, 8 warps/block
    const int epi_blocks = (NTOT / 16 + 3) / 4;    // 1 tile per warp, 4 warps/block

    k_zero<<<256, 256>>>(Wgc, Wbi);
    k_fill<<<(NEQ + 255) / 256, 256>>>(eu, ei);
    k_init<<<4096, 256>>>(ue, ie);

    static __half* whg_dev = nullptr;
    static __half* whb_dev = nullptr;
    if (!whg_dev) {
        cudaGetSymbolAddress((void**)&whg_dev, g_Whg);
        cudaGetSymbolAddress((void**)&whb_dev, g_Whb);
    }

    for (int l = 0; l < 3; l++) {
        k_stage1<<<stage_blocks, 256>>>();
        k_stage2<<<stage_blocks, 256>>>();
        k_epi<<<epi_blocks, 128>>>(whg_dev + l * 4096, bgc + l * 64,
                                   whb_dev + l * 4096, bbi + l * 64,
                                   out, l == 0 ? 1 : 0, l == 2 ? 1 : 0);
    }
}

// round 15
// speedup vs baseline: 1.0903x; 1.0262x over previous
#include <cuda_runtime.h>
#include <cuda_fp16.h>

#define NUQ 100000
#define NIQ 50000
#define NEQ 1000000
#define NTOT (NUQ + NIQ)
#define CSTR 64     // fixed CSR stride (P(deg>=64) ~ 1e-14; writes guarded)
#define WPITCH 72   // halves per smem W row (16B-aligned uint2 stores, conflict-free reads)

// ---------------- scratch (device globals; no allocation allowed) ----------------
__device__ int   g_cnt_u[NUQ];   // fill counters == degrees after k_fill
__device__ int   g_cnt_i[NIQ];
__device__ int   g_col_u[(size_t)NUQ * CSTR];   // per-user neighbor items
__device__ int   g_col_i[(size_t)NIQ * CSTR];   // per-item neighbor users
__device__ float g_su[NUQ], g_iu[NUQ];
__device__ float g_si[NIQ], g_ii[NIQ];
__device__ __half g_xh[(size_t)NTOT * 64];        // current embeddings (fp16)
__device__ __half g_scaled_h[(size_t)NTOT * 64];  // s_r * cur[r] (stage1 gather src)
__device__ __half g_E_h[(size_t)NTOT * 64];       // E (stage2 gather src)
__device__ __half g_acc[(size_t)NTOT * 64];       // running sum for the mean (fp16)
__device__ __half g_gh[(size_t)NTOT * 64];        // g (epi GEMM A operand)
__device__ __half g_Whg[3 * 4096];                // fp16 Wgc per layer
__device__ __half g_Whb[3 * 4096];                // fp16 Wbi per layer

// ---------------- helpers ----------------
__device__ __forceinline__ float lrelu(float x) { return x > 0.f ? x : 0.2f * x; }

__device__ __forceinline__ __half2 h2u(unsigned u) { return *reinterpret_cast<__half2*>(&u); }

__device__ __forceinline__ void acc_h8(float* a, uint4 q) {
    float2 f0 = __half22float2(h2u(q.x));
    float2 f1 = __half22float2(h2u(q.y));
    float2 f2 = __half22float2(h2u(q.z));
    float2 f3 = __half22float2(h2u(q.w));
    a[0] += f0.x; a[1] += f0.y; a[2] += f1.x; a[3] += f1.y;
    a[4] += f2.x; a[5] += f2.y; a[6] += f3.x; a[7] += f3.y;
}
// tree-reduce 4 rows of 8 halves in fp16 (depth 2), flush into fp32 accum
__device__ __forceinline__ void acc_h8x4(float* a, uint4 q0, uint4 q1, uint4 q2, uint4 q3) {
    __half2 sx = __hadd2(__hadd2(h2u(q0.x), h2u(q1.x)), __hadd2(h2u(q2.x), h2u(q3.x)));
    __half2 sy = __hadd2(__hadd2(h2u(q0.y), h2u(q1.y)), __hadd2(h2u(q2.y), h2u(q3.y)));
    __half2 sz = __hadd2(__hadd2(h2u(q0.z), h2u(q1.z)), __hadd2(h2u(q2.z), h2u(q3.z)));
    __half2 sw = __hadd2(__hadd2(h2u(q0.w), h2u(q1.w)), __hadd2(h2u(q2.w), h2u(q3.w)));
    float2 f0 = __half22float2(sx);
    float2 f1 = __half22float2(sy);
    float2 f2 = __half22float2(sz);
    float2 f3 = __half22float2(sw);
    a[0] += f0.x; a[1] += f0.y; a[2] += f1.x; a[3] += f1.y;
    a[4] += f2.x; a[5] += f2.y; a[6] += f3.x; a[7] += f3.y;
}
__device__ __forceinline__ uint4 pack_h8s(const float* a, float sc) {
    uint4 q;
    __half2 h0 = __floats2half2_rn(a[0] * sc, a[1] * sc);
    __half2 h1 = __floats2half2_rn(a[2] * sc, a[3] * sc);
    __half2 h2 = __floats2half2_rn(a[4] * sc, a[5] * sc);
    __half2 h3 = __floats2half2_rn(a[6] * sc, a[7] * sc);
    q.x = *reinterpret_cast<unsigned*>(&h0);
    q.y = *reinterpret_cast<unsigned*>(&h1);
    q.z = *reinterpret_cast<unsigned*>(&h2);
    q.w = *reinterpret_cast<unsigned*>(&h3);
    return q;
}
__device__ __forceinline__ uint2 pack_h4(float x, float y, float z, float w) {
    uint2 q;
    __half2 h0 = __floats2half2_rn(x, y);
    __half2 h1 = __floats2half2_rn(z, w);
    q.x = *reinterpret_cast<unsigned*>(&h0);
    q.y = *reinterpret_cast<unsigned*>(&h1);
    return q;
}
__device__ __forceinline__ void mma16816(float* c, const unsigned* a, const unsigned* b) {
    asm volatile(
        "mma.sync.aligned.m16n8k16.row.col.f32.f16.f16.f32 "
        "{%0,%1,%2,%3}, {%4,%5,%6,%7}, {%8,%9}, {%0,%1,%2,%3};\n"
        : "+f"(c[0]), "+f"(c[1]), "+f"(c[2]), "+f"(c[3])
        : "r"(a[0]), "r"(a[1]), "r"(a[2]), "r"(a[3]), "r"(b[0]), "r"(b[1]));
}

// ---------------- setup kernels ----------------
// zero counters + convert weights to fp16 (merged)
__global__ void k_zero(const float* __restrict__ Wgc, const float* __restrict__ Wbi) {
    int i = blockIdx.x * blockDim.x + threadIdx.x;
    int st = gridDim.x * blockDim.x;
    for (int j = i; j < NUQ; j += st) g_cnt_u[j] = 0;
    for (int j = i; j < NIQ; j += st) g_cnt_i[j] = 0;
    for (int j = i; j < 3 * 4096; j += st) {
        g_Whg[j] = __float2half(Wgc[j]);
        g_Whb[j] = __float2half(Wbi[j]);
    }
}

__global__ void k_fill(const int* __restrict__ eu, const int* __restrict__ ei) {
    int e = blockIdx.x * blockDim.x + threadIdx.x;
    if (e < NEQ) {
        int u = eu[e], it = ei[e];
        int ru = atomicAdd(&g_cnt_u[u], 1);
        if (ru < CSTR) g_col_u[(size_t)u * CSTR + ru] = it;
        int ri = atomicAdd(&g_cnt_i[it], 1);
        if (ri < CSTR) g_col_i[(size_t)it * CSTR + ri] = u;
    }
}

// init fp16 embeddings + scaled copy + degree scalars
__global__ void k_init(const float* __restrict__ ue, const float* __restrict__ ie) {
    int j = blockIdx.x * blockDim.x + threadIdx.x;
    int st = gridDim.x * blockDim.x;
    const int totu = NUQ * 16;
    const int tot = NTOT * 16;
    const float4* u4 = (const float4*)ue;
    const float4* i4 = (const float4*)ie;
    for (; j < tot; j += st) {
        float4 v = (j < totu) ? u4[j] : i4[j - totu];
        int row = j >> 4;
        int d = (row < NUQ) ? g_cnt_u[row] : g_cnt_i[row - NUQ];
        float s = d > 0 ? rsqrtf((float)d) : 0.f;
        if ((j & 15) == 0) {
            float inv = d > 0 ? 1.f / (float)d : 0.f;
            if (row < NUQ) { g_su[row] = s; g_iu[row] = inv; }
            else           { g_si[row - NUQ] = s; g_ii[row - NUQ] = inv; }
        }
        ((uint2*)g_xh)[j] = pack_h4(v.x, v.y, v.z, v.w);
        ((uint2*)g_scaled_h)[j] = pack_h4(v.x * s, v.y * s, v.z * s, v.w * s);
    }
}

// ---------------- graph stages: warp = 4 rows, 8 lanes x LDG.128 per row --------
__global__ __launch_bounds__(256, 7) void k_stage1() {
    int gw = (blockIdx.x * 256 + threadIdx.x) >> 5;
    int lane = threadIdx.x & 31;
    int sub = lane >> 3, l8 = lane & 7;
    int r = gw * 4 + sub;
    if (r >= NTOT) return;

    int deg;
    const int* col;
    const __half* src;
    float sc;
    __half* dst;
    if (r < NIQ) {            // item rows: E_items[i] = ii[i] * sum scaled_users
        deg = min(g_cnt_i[r], CSTR);
        col = g_col_i + (size_t)r * CSTR; src = g_scaled_h;
        sc = g_ii[r]; dst = g_E_h + (size_t)r * 64;
    } else {                  // user rows: E_users[u] = iu[u] * sum scaled_items
        int u = r - NIQ;
        deg = min(g_cnt_u[u], CSTR);
        col = g_col_u + (size_t)u * CSTR; src = g_scaled_h + (size_t)NUQ * 64;
        sc = g_iu[u]; dst = g_E_h + (size_t)(NIQ + u) * 64;
    }

    float a[8] = {0.f, 0.f, 0.f, 0.f, 0.f, 0.f, 0.f, 0.f};
    int e = 0;
    for (; e + 4 <= deg; e += 4) {
        int4 nn = *(const int4*)(col + e);   // 16B-aligned (CSTR%4==0, e%4==0)
        uint4 q0 = *(const uint4*)(src + (size_t)nn.x * 64 + l8 * 8);
        uint4 q1 = *(const uint4*)(src + (size_t)nn.y * 64 + l8 * 8);
        uint4 q2 = *(const uint4*)(src + (size_t)nn.z * 64 + l8 * 8);
        uint4 q3 = *(const uint4*)(src + (size_t)nn.w * 64 + l8 * 8);
        acc_h8x4(a, q0, q1, q2, q3);
    }
    for (; e < deg; e++) {
        int n = col[e];
        uint4 q = *(const uint4*)(src + (size_t)n * 64 + l8 * 8);
        acc_h8(a, q);
    }
    *(uint4*)(dst + l8 * 8) = pack_h8s(a, sc);
}

__global__ __launch_bounds__(256, 7) void k_stage2() {
    int gw = (blockIdx.x * 256 + threadIdx.x) >> 5;
    int lane = threadIdx.x & 31;
    int sub = lane >> 3, l8 = lane & 7;
    int r = gw * 4 + sub;
    if (r >= NTOT) return;

    int deg;
    const int* col;
    const __half* src;
    float sc;
    if (r < NUQ) {            // user rows: g_u = su[u] * sum E_items[neighbors]
        deg = min(g_cnt_u[r], CSTR);
        col = g_col_u + (size_t)r * CSTR; src = g_E_h; sc = g_su[r];
    } else {                  // item rows: g_i = si[i] * sum E_users[neighbors]
        int i = r - NUQ;
        deg = min(g_cnt_i[i], CSTR);
        col = g_col_i + (size_t)i * CSTR; src = g_E_h + (size_t)NIQ * 64; sc = g_si[i];
    }

    float a[8] = {0.f, 0.f, 0.f, 0.f, 0.f, 0.f, 0.f, 0.f};
    int e = 0;
    for (; e + 4 <= deg; e += 4) {
        int4 nn = *(const int4*)(col + e);
        uint4 q0 = *(const uint4*)(src + (size_t)nn.x * 64 + l8 * 8);
        uint4 q1 = *(const uint4*)(src + (size_t)nn.y * 64 + l8 * 8);
        uint4 q2 = *(const uint4*)(src + (size_t)nn.z * 64 + l8 * 8);
        uint4 q3 = *(const uint4*)(src + (size_t)nn.w * 64 + l8 * 8);
        acc_h8x4(a, q0, q1, q2, q3);
    }
    for (; e < deg; e++) {
        int n = col[e];
        uint4 q = *(const uint4*)(src + (size_t)n * 64 + l8 * 8);
        acc_h8(a, q);
    }
    *(uint4*)(g_gh + (size_t)r * 64 + l8 * 8) = pack_h8s(a, sc);
}

// ---------------- epilogue: tensor-core dual GEMM (p-frags via hmul2) ----------------
__global__ __launch_bounds__(128) void k_epi(const __half* __restrict__ Whg,
                                             const float* __restrict__ bgc,
                                             const __half* __restrict__ Whb,
                                             const float* __restrict__ bbi,
                                             float* __restrict__ out,
                                             int first, int last) {
    __shared__ __half sWg[64 * WPITCH];
    __shared__ __half sWb[64 * WPITCH];
    __shared__ float sbg[64], sbb[64];
    for (int i = threadIdx.x; i < 1024; i += 128) {
        int d = i >> 4, k4 = (i & 15) * 4;
        *(uint2*)&sWg[d * WPITCH + k4] = ((const uint2*)Whg)[i];
        *(uint2*)&sWb[d * WPITCH + k4] = ((const uint2*)Whb)[i];
    }
    if (threadIdx.x < 64) { sbg[threadIdx.x] = bgc[threadIdx.x]; sbb[threadIdx.x] = bbi[threadIdx.x]; }
    __syncthreads();

    int lane = threadIdx.x & 31;
    int gw = (blockIdx.x * 128 + threadIdx.x) >> 5;
    int nw = gridDim.x * 4;
    int qr = lane >> 2;          // 0..7
    int qc = (lane & 3) * 2;     // 0,2,4,6

    const int ntiles = NTOT / 16;   // 9375
    for (int t0 = gw; t0 < ntiles; t0 += nw) {
        int r0 = t0 * 16;
        int R0 = r0 + qr, R1 = R0 + 8;
        float cg[8][4], cp[8][4];
#pragma unroll
        for (int j = 0; j < 8; j++) {
#pragma unroll
            for (int q = 0; q < 4; q++) { cg[j][q] = 0.f; cp[j][q] = 0.f; }
        }
        // fused dual GEMM: D_g = g @ Wgc^T,  D_p = (g.*x) @ Wbi^T
#pragma unroll
        for (int t = 0; t < 4; t++) {
            int k0 = 16 * t + qc;
            unsigned ag[4], ax[4], ap[4];
            ag[0] = *(const unsigned*)(g_gh + (size_t)R0 * 64 + k0);
            ag[1] = *(const unsigned*)(g_gh + (size_t)R1 * 64 + k0);
            ag[2] = *(const unsigned*)(g_gh + (size_t)R0 * 64 + k0 + 8);
            ag[3] = *(const unsigned*)(g_gh + (size_t)R1 * 64 + k0 + 8);
            ax[0] = *(const unsigned*)(g_xh + (size_t)R0 * 64 + k0);
            ax[1] = *(const unsigned*)(g_xh + (size_t)R1 * 64 + k0);
            ax[2] = *(const unsigned*)(g_xh + (size_t)R0 * 64 + k0 + 8);
            ax[3] = *(const unsigned*)(g_xh + (size_t)R1 * 64 + k0 + 8);
#pragma unroll
            for (int q = 0; q < 4; q++) {
                __half2 hp = __hmul2(h2u(ag[q]), h2u(ax[q]));
                ap[q] = *reinterpret_cast<unsigned*>(&hp);
            }
#pragma unroll
            for (int j = 0; j < 8; j++) {
                const __half* wpg = &sWg[(8 * j + qr) * WPITCH + 16 * t + qc];
                const __half* wpb = &sWb[(8 * j + qr) * WPITCH + 16 * t + qc];
                unsigned bg[2], bb[2];
                bg[0] = *(const unsigned*)(wpg);
                bg[1] = *(const unsigned*)(wpg + 8);
                bb[0] = *(const unsigned*)(wpb);
                bb[1] = *(const unsigned*)(wpb + 8);
                mma16816(cg[j], ag, bg);
                mma16816(cp[j], ap, bb);
            }
        }
        // epilogue: y = lrelu(gc + bgc + x) + lrelu(bi + bbi); row-normalize; mean-acc
        float ssA = 0.f, ssB = 0.f;
#pragma unroll
        for (int j = 0; j < 8; j++) {
            int d0 = 8 * j + qc;
            float2 xA = __half22float2(*(const __half2*)(g_xh + (size_t)R0 * 64 + d0));
            float2 xB = __half22float2(*(const __half2*)(g_xh + (size_t)R1 * 64 + d0));
            float bg0 = sbg[d0], bg1 = sbg[d0 + 1];
            float bb0 = sbb[d0], bb1 = sbb[d0 + 1];
            float yA0 = lrelu(cg[j][0] + bg0 + xA.x) + lrelu(cp[j][0] + bb0);
            float yA1 = lrelu(cg[j][1] + bg1 + xA.y) + lrelu(cp[j][1] + bb1);
            float yB0 = lrelu(cg[j][2] + bg0 + xB.x) + lrelu(cp[j][2] + bb0);
            float yB1 = lrelu(cg[j][3] + bg1 + xB.y) + lrelu(cp[j][3] + bb1);
            cg[j][0] = yA0; cg[j][1] = yA1; cg[j][2] = yB0; cg[j][3] = yB1;
            // stash x in the now-dead cp fragments (used when first==1: acc==x)
            cp[j][0] = xA.x; cp[j][1] = xA.y; cp[j][2] = xB.x; cp[j][3] = xB.y;
            ssA += yA0 * yA0 + yA1 * yA1;
            ssB += yB0 * yB0 + yB1 * yB1;
        }
        ssA += __shfl_xor_sync(0xffffffffu, ssA, 1);
        ssA += __shfl_xor_sync(0xffffffffu, ssA, 2);
        ssB += __shfl_xor_sync(0xffffffffu, ssB, 1);
        ssB += __shfl_xor_sync(0xffffffffu, ssB, 2);
        float scA = 1.0f / fmaxf(sqrtf(ssA), 1e-12f);
        float scB = 1.0f / fmaxf(sqrtf(ssB), 1e-12f);
        float sA = 0.f, sB = 0.f;
        if (!last) {
            sA = (R0 < NUQ) ? g_su[R0] : g_si[R0 - NUQ];
            sB = (R1 < NUQ) ? g_su[R1] : g_si[R1 - NUQ];
        }
#pragma unroll
        for (int j = 0; j < 8; j++) {
            int d0 = 8 * j + qc;
            float yA0 = cg[j][0] * scA, yA1 = cg[j][1] * scA;
            float yB0 = cg[j][2] * scB, yB1 = cg[j][3] * scB;
            float2 aA, aB;
            if (first) {
                aA = make_float2(cp[j][0], cp[j][1]);
                aB = make_float2(cp[j][2], cp[j][3]);
            } else {
                aA = __half22float2(*(const __half2*)(g_acc + (size_t)R0 * 64 + d0));
                aB = __half22float2(*(const __half2*)(g_acc + (size_t)R1 * 64 + d0));
            }
            if (last) {
                *(float2*)(out + (size_t)R0 * 64 + d0) =
                    make_float2((aA.x + yA0) * 0.25f, (aA.y + yA1) * 0.25f);
                *(float2*)(out + (size_t)R1 * 64 + d0) =
                    make_float2((aB.x + yB0) * 0.25f, (aB.y + yB1) * 0.25f);
            } else {
                *(__half2*)(g_xh + (size_t)R0 * 64 + d0) = __floats2half2_rn(yA0, yA1);
                *(__half2*)(g_xh + (size_t)R1 * 64 + d0) = __floats2half2_rn(yB0, yB1);
                *(__half2*)(g_acc + (size_t)R0 * 64 + d0) = __floats2half2_rn(aA.x + yA0, aA.y + yA1);
                *(__half2*)(g_acc + (size_t)R1 * 64 + d0) = __floats2half2_rn(aB.x + yB0, aB.y + yB1);
                *(__half2*)(g_scaled_h + (size_t)R0 * 64 + d0) = __floats2half2_rn(yA0 * sA, yA1 * sA);
                *(__half2*)(g_scaled_h + (size_t)R1 * 64 + d0) = __floats2half2_rn(yB0 * sB, yB1 * sB);
            }
        }
    }
}

// ---------------- launch ----------------
extern "C" void kernel_launch(void* const* d_in, const int* in_sizes, int n_in,
                              void* d_out, int out_size) {
    const float* ue  = (const float*)d_in[0];
    const float* ie  = (const float*)d_in[1];
    const float* Wgc = (const float*)d_in[2];
    const float* bgc = (const float*)d_in[3];
    const float* Wbi = (const float*)d_in[4];
    const float* bbi = (const float*)d_in[5];
    const int*   eu  = (const int*)d_in[6];
    const int*   ei  = (const int*)d_in[7];
    float* out = (float*)d_out;

    const int stage_blocks = (NTOT / 4 + 7) / 8;     // 4 rows/warp, 8 warps/block
    const int epi_blocks = (NTOT / 16 + 7) / 8;      // 2 tiles per warp, 4 warps/block

    k_zero<<<256, 256>>>(Wgc, Wbi);
    k_fill<<<(NEQ + 255) / 256, 256>>>(eu, ei);
    k_init<<<4096, 256>>>(ue, ie);

    static __half* whg_dev = nullptr;
    static __half* whb_dev = nullptr;
    if (!whg_dev) {
        cudaGetSymbolAddress((void**)&whg_dev, g_Whg);
        cudaGetSymbolAddress((void**)&whb_dev, g_Whb);
    }

    for (int l = 0; l < 3; l++) {
        k_stage1<<<stage_blocks, 256>>>();
        k_stage2<<<stage_blocks, 256>>>();
        k_epi<<<epi_blocks, 128>>>(whg_dev + l * 4096, bgc + l * 64,
                                   whb_dev + l * 4096, bbi + l * 64,
                                   out, l == 0 ? 1 : 0, l == 2 ? 1 : 0);
    }
}

// round 16
// speedup vs baseline: 1.1086x; 1.0168x over previous
#include <cuda_runtime.h>
#include <cuda_fp16.h>

#define NUQ 100000
#define NIQ 50000
#define NEQ 1000000
#define NTOT (NUQ + NIQ)
#define CSTR 64     // fixed CSR stride (P(deg>=64) ~ 1e-14; writes guarded)
#define WPITCH 72   // halves per smem W row (16B-aligned uint2 stores, conflict-free reads)

// ---------------- scratch (device globals; no allocation allowed) ----------------
__device__ int   g_cnt_u[NUQ];   // fill counters == degrees after k_fill
__device__ int   g_cnt_i[NIQ];
__device__ int   g_col_u[(size_t)NUQ * CSTR];   // per-user neighbor items
__device__ int   g_col_i[(size_t)NIQ * CSTR];   // per-item neighbor users
__device__ float g_su[NUQ], g_iu[NUQ];
__device__ float g_si[NIQ], g_ii[NIQ];
__device__ __half g_xh[(size_t)NTOT * 64];        // current embeddings (fp16)
__device__ __half g_scaled_h[(size_t)NTOT * 64];  // s_r * cur[r] (stage1 gather src)
__device__ __half g_E_h[(size_t)NTOT * 64];       // E (stage2 gather src)
__device__ __half g_acc[(size_t)NTOT * 64];       // running sum for the mean (fp16)
__device__ __half g_gh[(size_t)NTOT * 64];        // g (epi GEMM A operand)
__device__ __half g_Whg[3 * 4096];                // fp16 Wgc per layer
__device__ __half g_Whb[3 * 4096];                // fp16 Wbi per layer

// ---------------- helpers ----------------
__device__ __forceinline__ float lrelu(float x) { return x > 0.f ? x : 0.2f * x; }

__device__ __forceinline__ __half2 h2u(unsigned u) { return *reinterpret_cast<__half2*>(&u); }

__device__ __forceinline__ void acc_h8(float* a, uint4 q) {
    float2 f0 = __half22float2(h2u(q.x));
    float2 f1 = __half22float2(h2u(q.y));
    float2 f2 = __half22float2(h2u(q.z));
    float2 f3 = __half22float2(h2u(q.w));
    a[0] += f0.x; a[1] += f0.y; a[2] += f1.x; a[3] += f1.y;
    a[4] += f2.x; a[5] += f2.y; a[6] += f3.x; a[7] += f3.y;
}
// tree-reduce 4 rows of 8 halves in fp16 (depth 2), flush into fp32 accum
__device__ __forceinline__ void acc_h8x4(float* a, uint4 q0, uint4 q1, uint4 q2, uint4 q3) {
    __half2 sx = __hadd2(__hadd2(h2u(q0.x), h2u(q1.x)), __hadd2(h2u(q2.x), h2u(q3.x)));
    __half2 sy = __hadd2(__hadd2(h2u(q0.y), h2u(q1.y)), __hadd2(h2u(q2.y), h2u(q3.y)));
    __half2 sz = __hadd2(__hadd2(h2u(q0.z), h2u(q1.z)), __hadd2(h2u(q2.z), h2u(q3.z)));
    __half2 sw = __hadd2(__hadd2(h2u(q0.w), h2u(q1.w)), __hadd2(h2u(q2.w), h2u(q3.w)));
    float2 f0 = __half22float2(sx);
    float2 f1 = __half22float2(sy);
    float2 f2 = __half22float2(sz);
    float2 f3 = __half22float2(sw);
    a[0] += f0.x; a[1] += f0.y; a[2] += f1.x; a[3] += f1.y;
    a[4] += f2.x; a[5] += f2.y; a[6] += f3.x; a[7] += f3.y;
}
__device__ __forceinline__ uint4 pack_h8s(const float* a, float sc) {
    uint4 q;
    __half2 h0 = __floats2half2_rn(a[0] * sc, a[1] * sc);
    __half2 h1 = __floats2half2_rn(a[2] * sc, a[3] * sc);
    __half2 h2 = __floats2half2_rn(a[4] * sc, a[5] * sc);
    __half2 h3 = __floats2half2_rn(a[6] * sc, a[7] * sc);
    q.x = *reinterpret_cast<unsigned*>(&h0);
    q.y = *reinterpret_cast<unsigned*>(&h1);
    q.z = *reinterpret_cast<unsigned*>(&h2);
    q.w = *reinterpret_cast<unsigned*>(&h3);
    return q;
}
__device__ __forceinline__ uint2 pack_h4(float x, float y, float z, float w) {
    uint2 q;
    __half2 h0 = __floats2half2_rn(x, y);
    __half2 h1 = __floats2half2_rn(z, w);
    q.x = *reinterpret_cast<unsigned*>(&h0);
    q.y = *reinterpret_cast<unsigned*>(&h1);
    return q;
}
__device__ __forceinline__ void mma16816(float* c, const unsigned* a, const unsigned* b) {
    asm volatile(
        "mma.sync.aligned.m16n8k16.row.col.f32.f16.f16.f32 "
        "{%0,%1,%2,%3}, {%4,%5,%6,%7}, {%8,%9}, {%0,%1,%2,%3};\n"
        : "+f"(c[0]), "+f"(c[1]), "+f"(c[2]), "+f"(c[3])
        : "r"(a[0]), "r"(a[1]), "r"(a[2]), "r"(a[3]), "r"(b[0]), "r"(b[1]));
}

// ---------------- setup kernels ----------------
// zero counters + convert weights to fp16 (merged)
__global__ void k_zero(const float* __restrict__ Wgc, const float* __restrict__ Wbi) {
    int i = blockIdx.x * blockDim.x + threadIdx.x;
    int st = gridDim.x * blockDim.x;
    for (int j = i; j < NUQ; j += st) g_cnt_u[j] = 0;
    for (int j = i; j < NIQ; j += st) g_cnt_i[j] = 0;
    for (int j = i; j < 3 * 4096; j += st) {
        g_Whg[j] = __float2half(Wgc[j]);
        g_Whb[j] = __float2half(Wbi[j]);
    }
}

__global__ void k_fill(const int* __restrict__ eu, const int* __restrict__ ei) {
    int e = blockIdx.x * blockDim.x + threadIdx.x;
    if (e < NEQ) {
        int u = eu[e], it = ei[e];
        int ru = atomicAdd(&g_cnt_u[u], 1);
        if (ru < CSTR) g_col_u[(size_t)u * CSTR + ru] = it;
        int ri = atomicAdd(&g_cnt_i[it], 1);
        if (ri < CSTR) g_col_i[(size_t)it * CSTR + ri] = u;
    }
}

// init fp16 embeddings + scaled copy + degree scalars
__global__ void k_init(const float* __restrict__ ue, const float* __restrict__ ie) {
    int j = blockIdx.x * blockDim.x + threadIdx.x;
    int st = gridDim.x * blockDim.x;
    const int totu = NUQ * 16;
    const int tot = NTOT * 16;
    const float4* u4 = (const float4*)ue;
    const float4* i4 = (const float4*)ie;
    for (; j < tot; j += st) {
        float4 v = (j < totu) ? u4[j] : i4[j - totu];
        int row = j >> 4;
        int d = (row < NUQ) ? g_cnt_u[row] : g_cnt_i[row - NUQ];
        float s = d > 0 ? rsqrtf((float)d) : 0.f;
        if ((j & 15) == 0) {
            float inv = d > 0 ? 1.f / (float)d : 0.f;
            if (row < NUQ) { g_su[row] = s; g_iu[row] = inv; }
            else           { g_si[row - NUQ] = s; g_ii[row - NUQ] = inv; }
        }
        ((uint2*)g_xh)[j] = pack_h4(v.x, v.y, v.z, v.w);
        ((uint2*)g_scaled_h)[j] = pack_h4(v.x * s, v.y * s, v.z * s, v.w * s);
    }
}

// ---------------- graph stages: warp = 4 rows, 8 lanes x LDG.128 per row --------
__global__ __launch_bounds__(256, 6) void k_stage1() {
    int gw = (blockIdx.x * 256 + threadIdx.x) >> 5;
    int lane = threadIdx.x & 31;
    int sub = lane >> 3, l8 = lane & 7;
    int r = gw * 4 + sub;
    if (r >= NTOT) return;

    int deg;
    const int* col;
    const __half* src;
    float sc;
    __half* dst;
    if (r < NIQ) {            // item rows: E_items[i] = ii[i] * sum scaled_users
        deg = min(g_cnt_i[r], CSTR);
        col = g_col_i + (size_t)r * CSTR; src = g_scaled_h;
        sc = g_ii[r]; dst = g_E_h + (size_t)r * 64;
    } else {                  // user rows: E_users[u] = iu[u] * sum scaled_items
        int u = r - NIQ;
        deg = min(g_cnt_u[u], CSTR);
        col = g_col_u + (size_t)u * CSTR; src = g_scaled_h + (size_t)NUQ * 64;
        sc = g_iu[u]; dst = g_E_h + (size_t)(NIQ + u) * 64;
    }

    float a[8] = {0.f, 0.f, 0.f, 0.f, 0.f, 0.f, 0.f, 0.f};
    int e = 0;
    for (; e + 4 <= deg; e += 4) {
        int4 nn = *(const int4*)(col + e);   // 16B-aligned (CSTR%4==0, e%4==0)
        uint4 q0 = *(const uint4*)(src + (size_t)nn.x * 64 + l8 * 8);
        uint4 q1 = *(const uint4*)(src + (size_t)nn.y * 64 + l8 * 8);
        uint4 q2 = *(const uint4*)(src + (size_t)nn.z * 64 + l8 * 8);
        uint4 q3 = *(const uint4*)(src + (size_t)nn.w * 64 + l8 * 8);
        acc_h8x4(a, q0, q1, q2, q3);
    }
    for (; e < deg; e++) {
        int n = col[e];
        uint4 q = *(const uint4*)(src + (size_t)n * 64 + l8 * 8);
        acc_h8(a, q);
    }
    *(uint4*)(dst + l8 * 8) = pack_h8s(a, sc);
}

__global__ __launch_bounds__(256, 6) void k_stage2() {
    int gw = (blockIdx.x * 256 + threadIdx.x) >> 5;
    int lane = threadIdx.x & 31;
    int sub = lane >> 3, l8 = lane & 7;
    int r = gw * 4 + sub;
    if (r >= NTOT) return;

    int deg;
    const int* col;
    const __half* src;
    float sc;
    if (r < NUQ) {            // user rows: g_u = su[u] * sum E_items[neighbors]
        deg = min(g_cnt_u[r], CSTR);
        col = g_col_u + (size_t)r * CSTR; src = g_E_h; sc = g_su[r];
    } else {                  // item rows: g_i = si[i] * sum E_users[neighbors]
        int i = r - NUQ;
        deg = min(g_cnt_i[i], CSTR);
        col = g_col_i + (size_t)i * CSTR; src = g_E_h + (size_t)NIQ * 64; sc = g_si[i];
    }

    float a[8] = {0.f, 0.f, 0.f, 0.f, 0.f, 0.f, 0.f, 0.f};
    int e = 0;
    for (; e + 4 <= deg; e += 4) {
        int4 nn = *(const int4*)(col + e);
        uint4 q0 = *(const uint4*)(src + (size_t)nn.x * 64 + l8 * 8);
        uint4 q1 = *(const uint4*)(src + (size_t)nn.y * 64 + l8 * 8);
        uint4 q2 = *(const uint4*)(src + (size_t)nn.z * 64 + l8 * 8);
        uint4 q3 = *(const uint4*)(src + (size_t)nn.w * 64 + l8 * 8);
        acc_h8x4(a, q0, q1, q2, q3);
    }
    for (; e < deg; e++) {
        int n = col[e];
        uint4 q = *(const uint4*)(src + (size_t)n * 64 + l8 * 8);
        acc_h8(a, q);
    }
    *(uint4*)(g_gh + (size_t)r * 64 + l8 * 8) = pack_h8s(a, sc);
}

// ---------------- epilogue: tensor-core dual GEMM (p-frags via hmul2) ----------------
__global__ __launch_bounds__(128) void k_epi(const __half* __restrict__ Whg,
                                             const float* __restrict__ bgc,
                                             const __half* __restrict__ Whb,
                                             const float* __restrict__ bbi,
                                             float* __restrict__ out,
                                             int first, int last) {
    __shared__ __half sWg[64 * WPITCH];
    __shared__ __half sWb[64 * WPITCH];
    __shared__ float sbg[64], sbb[64];
    for (int i = threadIdx.x; i < 1024; i += 128) {
        int d = i >> 4, k4 = (i & 15) * 4;
        *(uint2*)&sWg[d * WPITCH + k4] = ((const uint2*)Whg)[i];
        *(uint2*)&sWb[d * WPITCH + k4] = ((const uint2*)Whb)[i];
    }
    if (threadIdx.x < 64) { sbg[threadIdx.x] = bgc[threadIdx.x]; sbb[threadIdx.x] = bbi[threadIdx.x]; }
    __syncthreads();

    int lane = threadIdx.x & 31;
    int gw = (blockIdx.x * 128 + threadIdx.x) >> 5;
    int nw = gridDim.x * 4;
    int qr = lane >> 2;          // 0..7
    int qc = (lane & 3) * 2;     // 0,2,4,6

    const int ntiles = NTOT / 16;   // 9375
    for (int t0 = gw; t0 < ntiles; t0 += nw) {
        int r0 = t0 * 16;
        int R0 = r0 + qr, R1 = R0 + 8;
        float cg[8][4], cp[8][4];
#pragma unroll
        for (int j = 0; j < 8; j++) {
#pragma unroll
            for (int q = 0; q < 4; q++) { cg[j][q] = 0.f; cp[j][q] = 0.f; }
        }
        // fused dual GEMM: D_g = g @ Wgc^T,  D_p = (g.*x) @ Wbi^T
#pragma unroll
        for (int t = 0; t < 4; t++) {
            int k0 = 16 * t + qc;
            unsigned ag[4], ax[4], ap[4];
            ag[0] = *(const unsigned*)(g_gh + (size_t)R0 * 64 + k0);
            ag[1] = *(const unsigned*)(g_gh + (size_t)R1 * 64 + k0);
            ag[2] = *(const unsigned*)(g_gh + (size_t)R0 * 64 + k0 + 8);
            ag[3] = *(const unsigned*)(g_gh + (size_t)R1 * 64 + k0 + 8);
            ax[0] = *(const unsigned*)(g_xh + (size_t)R0 * 64 + k0);
            ax[1] = *(const unsigned*)(g_xh + (size_t)R1 * 64 + k0);
            ax[2] = *(const unsigned*)(g_xh + (size_t)R0 * 64 + k0 + 8);
            ax[3] = *(const unsigned*)(g_xh + (size_t)R1 * 64 + k0 + 8);
#pragma unroll
            for (int q = 0; q < 4; q++) {
                __half2 hp = __hmul2(h2u(ag[q]), h2u(ax[q]));
                ap[q] = *reinterpret_cast<unsigned*>(&hp);
            }
#pragma unroll
            for (int j = 0; j < 8; j++) {
                const __half* wpg = &sWg[(8 * j + qr) * WPITCH + 16 * t + qc];
                const __half* wpb = &sWb[(8 * j + qr) * WPITCH + 16 * t + qc];
                unsigned bg[2], bb[2];
                bg[0] = *(const unsigned*)(wpg);
                bg[1] = *(const unsigned*)(wpg + 8);
                bb[0] = *(const unsigned*)(wpb);
                bb[1] = *(const unsigned*)(wpb + 8);
                mma16816(cg[j], ag, bg);
                mma16816(cp[j], ap, bb);
            }
        }
        // epilogue: y = lrelu(gc + bgc + x) + lrelu(bi + bbi); row-normalize; mean-acc
        float ssA = 0.f, ssB = 0.f;
#pragma unroll
        for (int j = 0; j < 8; j++) {
            int d0 = 8 * j + qc;
            float2 xA = __half22float2(*(const __half2*)(g_xh + (size_t)R0 * 64 + d0));
            float2 xB = __half22float2(*(const __half2*)(g_xh + (size_t)R1 * 64 + d0));
            float bg0 = sbg[d0], bg1 = sbg[d0 + 1];
            float bb0 = sbb[d0], bb1 = sbb[d0 + 1];
            float yA0 = lrelu(cg[j][0] + bg0 + xA.x) + lrelu(cp[j][0] + bb0);
            float yA1 = lrelu(cg[j][1] + bg1 + xA.y) + lrelu(cp[j][1] + bb1);
            float yB0 = lrelu(cg[j][2] + bg0 + xB.x) + lrelu(cp[j][2] + bb0);
            float yB1 = lrelu(cg[j][3] + bg1 + xB.y) + lrelu(cp[j][3] + bb1);
            cg[j][0] = yA0; cg[j][1] = yA1; cg[j][2] = yB0; cg[j][3] = yB1;
            // stash x in the now-dead cp fragments (used when first==1: acc==x)
            cp[j][0] = xA.x; cp[j][1] = xA.y; cp[j][2] = xB.x; cp[j][3] = xB.y;
            ssA += yA0 * yA0 + yA1 * yA1;
            ssB += yB0 * yB0 + yB1 * yB1;
        }
        ssA += __shfl_xor_sync(0xffffffffu, ssA, 1);
        ssA += __shfl_xor_sync(0xffffffffu, ssA, 2);
        ssB += __shfl_xor_sync(0xffffffffu, ssB, 1);
        ssB += __shfl_xor_sync(0xffffffffu, ssB, 2);
        float scA = 1.0f / fmaxf(sqrtf(ssA), 1e-12f);
        float scB = 1.0f / fmaxf(sqrtf(ssB), 1e-12f);
        float sA = 0.f, sB = 0.f;
        if (!last) {
            sA = (R0 < NUQ) ? g_su[R0] : g_si[R0 - NUQ];
            sB = (R1 < NUQ) ? g_su[R1] : g_si[R1 - NUQ];
        }
#pragma unroll
        for (int j = 0; j < 8; j++) {
            int d0 = 8 * j + qc;
            float yA0 = cg[j][0] * scA, yA1 = cg[j][1] * scA;
            float yB0 = cg[j][2] * scB, yB1 = cg[j][3] * scB;
            float2 aA, aB;
            if (first) {
                aA = make_float2(cp[j][0], cp[j][1]);
                aB = make_float2(cp[j][2], cp[j][3]);
            } else {
                aA = __half22float2(*(const __half2*)(g_acc + (size_t)R0 * 64 + d0));
                aB = __half22float2(*(const __half2*)(g_acc + (size_t)R1 * 64 + d0));
            }
            if (last) {
                *(float2*)(out + (size_t)R0 * 64 + d0) =
                    make_float2((aA.x + yA0) * 0.25f, (aA.y + yA1) * 0.25f);
                *(float2*)(out + (size_t)R1 * 64 + d0) =
                    make_float2((aB.x + yB0) * 0.25f, (aB.y + yB1) * 0.25f);
            } else {
                *(__half2*)(g_xh + (size_t)R0 * 64 + d0) = __floats2half2_rn(yA0, yA1);
                *(__half2*)(g_xh + (size_t)R1 * 64 + d0) = __floats2half2_rn(yB0, yB1);
                *(__half2*)(g_acc + (size_t)R0 * 64 + d0) = __floats2half2_rn(aA.x + yA0, aA.y + yA1);
                *(__half2*)(g_acc + (size_t)R1 * 64 + d0) = __floats2half2_rn(aB.x + yB0, aB.y + yB1);
                *(__half2*)(g_scaled_h + (size_t)R0 * 64 + d0) = __floats2half2_rn(yA0 * sA, yA1 * sA);
                *(__half2*)(g_scaled_h + (size_t)R1 * 64 + d0) = __floats2half2_rn(yB0 * sB, yB1 * sB);
            }
        }
    }
}

// ---------------- launch ----------------
extern "C" void kernel_launch(void* const* d_in, const int* in_sizes, int n_in,
                              void* d_out, int out_size) {
    const float* ue  = (const float*)d_in[0];
    const float* ie  = (const float*)d_in[1];
    const float* Wgc = (const float*)d_in[2];
    const float* bgc = (const float*)d_in[3];
    const float* Wbi = (const float*)d_in[4];
    const float* bbi = (const float*)d_in[5];
    const int*   eu  = (const int*)d_in[6];
    const int*   ei  = (const int*)d_in[7];
    float* out = (float*)d_out;

    const int stage_blocks = (NTOT / 4 + 7) / 8;     // 4 rows/warp, 8 warps/block
    const int epi_blocks = (NTOT / 16 + 15) / 16;    // 4 tiles per warp, 4 warps/block

    k_zero<<<256, 256>>>(Wgc, Wbi);
    k_fill<<<(NEQ + 255) / 256, 256>>>(eu, ei);
    k_init<<<4096, 256>>>(ue, ie);

    static __half* whg_dev = nullptr;
    static __half* whb_dev = nullptr;
    if (!whg_dev) {
        cudaGetSymbolAddress((void**)&whg_dev, g_Whg);
        cudaGetSymbolAddress((void**)&whb_dev, g_Whb);
    }

    for (int l = 0; l < 3; l++) {
        k_stage1<<<stage_blocks, 256>>>();
        k_stage2<<<stage_blocks, 256>>>();
        k_epi<<<epi_blocks, 128>>>(whg_dev + l * 4096, bgc + l * 64,
                                   whb_dev + l * 4096, bbi + l * 64,
                                   out, l == 0 ? 1 : 0, l == 2 ? 1 : 0);
    }
}

// round 17
// speedup vs baseline: 1.1097x; 1.0009x over previous
#include <cuda_runtime.h>
#include <cuda_fp16.h>

#define NUQ 100000
#define NIQ 50000
#define NEQ 1000000
#define NTOT (NUQ + NIQ)
#define CSTR 64     // fixed CSR stride (P(deg>=64) ~ 1e-14; writes guarded)
#define WPITCH 72   // halves per smem W row (16B-aligned uint2 stores, conflict-free reads)
#define NBIN 65     // degree buckets 0..64

// ---------------- scratch (device globals; no allocation allowed) ----------------
__device__ int   g_cnt_u[NUQ];   // fill counters == degrees after k_fill
__device__ int   g_cnt_i[NIQ];
__device__ int   g_col_u[(size_t)NUQ * CSTR];   // per-user neighbor items
__device__ int   g_col_i[(size_t)NIQ * CSTR];   // per-item neighbor users
__device__ int   g_hist[NBIN];
__device__ int   g_hcur[NBIN];
__device__ int   g_perm[NTOT];   // rows sorted by degree (warp load balance)
__device__ float g_su[NUQ], g_iu[NUQ];
__device__ float g_si[NIQ], g_ii[NIQ];
__device__ __half g_xh[(size_t)NTOT * 64];        // current embeddings (fp16)
__device__ __half g_scaled_h[(size_t)NTOT * 64];  // s_r * cur[r] (stage1 gather src)
__device__ __half g_E_h[(size_t)NTOT * 64];       // E (stage2 gather src)
__device__ __half g_acc[(size_t)NTOT * 64];       // running sum for the mean (fp16)
__device__ __half g_gh[(size_t)NTOT * 64];        // g (epi GEMM A operand)
__device__ __half g_Whg[3 * 4096];                // fp16 Wgc per layer
__device__ __half g_Whb[3 * 4096];                // fp16 Wbi per layer

// ---------------- helpers ----------------
__device__ __forceinline__ float lrelu(float x) { return x > 0.f ? x : 0.2f * x; }

__device__ __forceinline__ __half2 h2u(unsigned u) { return *reinterpret_cast<__half2*>(&u); }

__device__ __forceinline__ void acc_h8(float* a, uint4 q) {
    float2 f0 = __half22float2(h2u(q.x));
    float2 f1 = __half22float2(h2u(q.y));
    float2 f2 = __half22float2(h2u(q.z));
    float2 f3 = __half22float2(h2u(q.w));
    a[0] += f0.x; a[1] += f0.y; a[2] += f1.x; a[3] += f1.y;
    a[4] += f2.x; a[5] += f2.y; a[6] += f3.x; a[7] += f3.y;
}
// tree-reduce 4 rows of 8 halves in fp16 (depth 2), flush into fp32 accum
__device__ __forceinline__ void acc_h8x4(float* a, uint4 q0, uint4 q1, uint4 q2, uint4 q3) {
    __half2 sx = __hadd2(__hadd2(h2u(q0.x), h2u(q1.x)), __hadd2(h2u(q2.x), h2u(q3.x)));
    __half2 sy = __hadd2(__hadd2(h2u(q0.y), h2u(q1.y)), __hadd2(h2u(q2.y), h2u(q3.y)));
    __half2 sz = __hadd2(__hadd2(h2u(q0.z), h2u(q1.z)), __hadd2(h2u(q2.z), h2u(q3.z)));
    __half2 sw = __hadd2(__hadd2(h2u(q0.w), h2u(q1.w)), __hadd2(h2u(q2.w), h2u(q3.w)));
    float2 f0 = __half22float2(sx);
    float2 f1 = __half22float2(sy);
    float2 f2 = __half22float2(sz);
    float2 f3 = __half22float2(sw);
    a[0] += f0.x; a[1] += f0.y; a[2] += f1.x; a[3] += f1.y;
    a[4] += f2.x; a[5] += f2.y; a[6] += f3.x; a[7] += f3.y;
}
__device__ __forceinline__ uint4 pack_h8s(const float* a, float sc) {
    uint4 q;
    __half2 h0 = __floats2half2_rn(a[0] * sc, a[1] * sc);
    __half2 h1 = __floats2half2_rn(a[2] * sc, a[3] * sc);
    __half2 h2 = __floats2half2_rn(a[4] * sc, a[5] * sc);
    __half2 h3 = __floats2half2_rn(a[6] * sc, a[7] * sc);
    q.x = *reinterpret_cast<unsigned*>(&h0);
    q.y = *reinterpret_cast<unsigned*>(&h1);
    q.z = *reinterpret_cast<unsigned*>(&h2);
    q.w = *reinterpret_cast<unsigned*>(&h3);
    return q;
}
__device__ __forceinline__ uint2 pack_h4(float x, float y, float z, float w) {
    uint2 q;
    __half2 h0 = __floats2half2_rn(x, y);
    __half2 h1 = __floats2half2_rn(z, w);
    q.x = *reinterpret_cast<unsigned*>(&h0);
    q.y = *reinterpret_cast<unsigned*>(&h1);
    return q;
}
__device__ __forceinline__ void mma16816(float* c, const unsigned* a, const unsigned* b) {
    asm volatile(
        "mma.sync.aligned.m16n8k16.row.col.f32.f16.f16.f32 "
        "{%0,%1,%2,%3}, {%4,%5,%6,%7}, {%8,%9}, {%0,%1,%2,%3};\n"
        : "+f"(c[0]), "+f"(c[1]), "+f"(c[2]), "+f"(c[3])
        : "r"(a[0]), "r"(a[1]), "r"(a[2]), "r"(a[3]), "r"(b[0]), "r"(b[1]));
}

__device__ __forceinline__ int row_deg(int rho) {
    return min(rho < NUQ ? g_cnt_u[rho] : g_cnt_i[rho - NUQ], CSTR);
}

// ---------------- setup kernels ----------------
// zero counters + hist + convert weights to fp16 (merged)
__global__ void k_zero(const float* __restrict__ Wgc, const float* __restrict__ Wbi) {
    int i = blockIdx.x * blockDim.x + threadIdx.x;
    int st = gridDim.x * blockDim.x;
    for (int j = i; j < NUQ; j += st) g_cnt_u[j] = 0;
    for (int j = i; j < NIQ; j += st) g_cnt_i[j] = 0;
    if (i < NBIN) g_hist[i] = 0;
    for (int j = i; j < 3 * 4096; j += st) {
        g_Whg[j] = __float2half(Wgc[j]);
        g_Whb[j] = __float2half(Wbi[j]);
    }
}

__global__ void k_fill(const int* __restrict__ eu, const int* __restrict__ ei) {
    int e = blockIdx.x * blockDim.x + threadIdx.x;
    if (e < NEQ) {
        int u = eu[e], it = ei[e];
        int ru = atomicAdd(&g_cnt_u[u], 1);
        if (ru < CSTR) g_col_u[(size_t)u * CSTR + ru] = it;
        int ri = atomicAdd(&g_cnt_i[it], 1);
        if (ri < CSTR) g_col_i[(size_t)it * CSTR + ri] = u;
    }
}

// degree histogram (block-local smem, then flush)
__global__ void k_hist() {
    __shared__ int sh[NBIN];
    int t = threadIdx.x;
    if (t < NBIN) sh[t] = 0;
    __syncthreads();
    int rho = blockIdx.x * 256 + t;
    if (rho < NTOT) atomicAdd(&sh[row_deg(rho)], 1);
    __syncthreads();
    if (t < NBIN && sh[t]) atomicAdd(&g_hist[t], sh[t]);
}

// exclusive scan of 65 bins (single block)
__global__ void k_hscan() {
    __shared__ int s[NBIN];
    int t = threadIdx.x;
    if (t < NBIN) s[t] = g_hist[t];
    __syncthreads();
    if (t == 0) {
        int acc = 0;
        for (int d = 0; d < NBIN; d++) { int v = s[d]; s[d] = acc; acc += v; }
    }
    __syncthreads();
    if (t < NBIN) g_hcur[t] = s[t];
}

// scatter rows into degree-sorted permutation (hierarchical allocation)
__global__ void k_scatter() {
    __shared__ int cnt[NBIN], base[NBIN];
    int t = threadIdx.x;
    if (t < NBIN) cnt[t] = 0;
    __syncthreads();
    int rho = blockIdx.x * 256 + t;
    int d = 0, loc = 0;
    bool v = rho < NTOT;
    if (v) { d = row_deg(rho); loc = atomicAdd(&cnt[d], 1); }
    __syncthreads();
    if (t < NBIN && cnt[t]) base[t] = atomicAdd(&g_hcur[t], cnt[t]);
    __syncthreads();
    if (v) g_perm[base[d] + loc] = rho;
}

// init fp16 embeddings + scaled copy + degree scalars
__global__ void k_init(const float* __restrict__ ue, const float* __restrict__ ie) {
    int j = blockIdx.x * blockDim.x + threadIdx.x;
    int st = gridDim.x * blockDim.x;
    const int totu = NUQ * 16;
    const int tot = NTOT * 16;
    const float4* u4 = (const float4*)ue;
    const float4* i4 = (const float4*)ie;
    for (; j < tot; j += st) {
        float4 v = (j < totu) ? u4[j] : i4[j - totu];
        int row = j >> 4;
        int d = (row < NUQ) ? g_cnt_u[row] : g_cnt_i[row - NUQ];
        float s = d > 0 ? rsqrtf((float)d) : 0.f;
        if ((j & 15) == 0) {
            float inv = d > 0 ? 1.f / (float)d : 0.f;
            if (row < NUQ) { g_su[row] = s; g_iu[row] = inv; }
            else           { g_si[row - NUQ] = s; g_ii[row - NUQ] = inv; }
        }
        ((uint2*)g_xh)[j] = pack_h4(v.x, v.y, v.z, v.w);
        ((uint2*)g_scaled_h)[j] = pack_h4(v.x * s, v.y * s, v.z * s, v.w * s);
    }
}

// ---------------- graph stages: warp = 4 deg-sorted rows, 8 lanes x LDG.128 --------
__global__ __launch_bounds__(256, 6) void k_stage1() {
    int gw = (blockIdx.x * 256 + threadIdx.x) >> 5;
    int lane = threadIdx.x & 31;
    int sub = lane >> 3, l8 = lane & 7;
    int task = gw * 4 + sub;
    if (task >= NTOT) return;
    int rho = g_perm[task];

    int deg;
    const int* col;
    const __half* src;
    float sc;
    __half* dst;
    if (rho < NUQ) {          // user u: E_users[u] = iu[u] * sum scaled_items
        deg = min(g_cnt_u[rho], CSTR);
        col = g_col_u + (size_t)rho * CSTR; src = g_scaled_h + (size_t)NUQ * 64;
        sc = g_iu[rho]; dst = g_E_h + (size_t)(NIQ + rho) * 64;
    } else {                  // item i: E_items[i] = ii[i] * sum scaled_users
        int i = rho - NUQ;
        deg = min(g_cnt_i[i], CSTR);
        col = g_col_i + (size_t)i * CSTR; src = g_scaled_h;
        sc = g_ii[i]; dst = g_E_h + (size_t)i * 64;
    }

    float a[8] = {0.f, 0.f, 0.f, 0.f, 0.f, 0.f, 0.f, 0.f};
    int e = 0;
    for (; e + 4 <= deg; e += 4) {
        int4 nn = *(const int4*)(col + e);   // 16B-aligned (CSTR%4==0, e%4==0)
        uint4 q0 = *(const uint4*)(src + (size_t)nn.x * 64 + l8 * 8);
        uint4 q1 = *(const uint4*)(src + (size_t)nn.y * 64 + l8 * 8);
        uint4 q2 = *(const uint4*)(src + (size_t)nn.z * 64 + l8 * 8);
        uint4 q3 = *(const uint4*)(src + (size_t)nn.w * 64 + l8 * 8);
        acc_h8x4(a, q0, q1, q2, q3);
    }
    for (; e < deg; e++) {
        int n = col[e];
        uint4 q = *(const uint4*)(src + (size_t)n * 64 + l8 * 8);
        acc_h8(a, q);
    }
    *(uint4*)(dst + l8 * 8) = pack_h8s(a, sc);
}

__global__ __launch_bounds__(256, 6) void k_stage2() {
    int gw = (blockIdx.x * 256 + threadIdx.x) >> 5;
    int lane = threadIdx.x & 31;
    int sub = lane >> 3, l8 = lane & 7;
    int task = gw * 4 + sub;
    if (task >= NTOT) return;
    int rho = g_perm[task];

    int deg;
    const int* col;
    const __half* src;
    float sc;
    if (rho < NUQ) {          // user: g_u = su[u] * sum E_items[neighbors]
        deg = min(g_cnt_u[rho], CSTR);
        col = g_col_u + (size_t)rho * CSTR; src = g_E_h; sc = g_su[rho];
    } else {                  // item: g_i = si[i] * sum E_users[neighbors]
        int i = rho - NUQ;
        deg = min(g_cnt_i[i], CSTR);
        col = g_col_i + (size_t)i * CSTR; src = g_E_h + (size_t)NIQ * 64; sc = g_si[i];
    }

    float a[8] = {0.f, 0.f, 0.f, 0.f, 0.f, 0.f, 0.f, 0.f};
    int e = 0;
    for (; e + 4 <= deg; e += 4) {
        int4 nn = *(const int4*)(col + e);
        uint4 q0 = *(const uint4*)(src + (size_t)nn.x * 64 + l8 * 8);
        uint4 q1 = *(const uint4*)(src + (size_t)nn.y * 64 + l8 * 8);
        uint4 q2 = *(const uint4*)(src + (size_t)nn.z * 64 + l8 * 8);
        uint4 q3 = *(const uint4*)(src + (size_t)nn.w * 64 + l8 * 8);
        acc_h8x4(a, q0, q1, q2, q3);
    }
    for (; e < deg; e++) {
        int n = col[e];
        uint4 q = *(const uint4*)(src + (size_t)n * 64 + l8 * 8);
        acc_h8(a, q);
    }
    *(uint4*)(g_gh + (size_t)rho * 64 + l8 * 8) = pack_h8s(a, sc);
}

// ---------------- epilogue: tensor-core dual GEMM (p-frags via hmul2) ----------------
__global__ __launch_bounds__(128) void k_epi(const __half* __restrict__ Whg,
                                             const float* __restrict__ bgc,
                                             const __half* __restrict__ Whb,
                                             const float* __restrict__ bbi,
                                             float* __restrict__ out,
                                             int first, int last) {
    __shared__ __half sWg[64 * WPITCH];
    __shared__ __half sWb[64 * WPITCH];
    __shared__ float sbg[64], sbb[64];
    for (int i = threadIdx.x; i < 1024; i += 128) {
        int d = i >> 4, k4 = (i & 15) * 4;
        *(uint2*)&sWg[d * WPITCH + k4] = ((const uint2*)Whg)[i];
        *(uint2*)&sWb[d * WPITCH + k4] = ((const uint2*)Whb)[i];
    }
    if (threadIdx.x < 64) { sbg[threadIdx.x] = bgc[threadIdx.x]; sbb[threadIdx.x] = bbi[threadIdx.x]; }
    __syncthreads();

    int lane = threadIdx.x & 31;
    int gw = (blockIdx.x * 128 + threadIdx.x) >> 5;
    int nw = gridDim.x * 4;
    int qr = lane >> 2;          // 0..7
    int qc = (lane & 3) * 2;     // 0,2,4,6

    const int ntiles = NTOT / 16;   // 9375
    for (int t0 = gw; t0 < ntiles; t0 += nw) {
        int r0 = t0 * 16;
        int R0 = r0 + qr, R1 = R0 + 8;
        float cg[8][4], cp[8][4];
#pragma unroll
        for (int j = 0; j < 8; j++) {
#pragma unroll
            for (int q = 0; q < 4; q++) { cg[j][q] = 0.f; cp[j][q] = 0.f; }
        }
        // fused dual GEMM: D_g = g @ Wgc^T,  D_p = (g.*x) @ Wbi^T
#pragma unroll
        for (int t = 0; t < 4; t++) {
            int k0 = 16 * t + qc;
            unsigned ag[4], ax[4], ap[4];
            ag[0] = *(const unsigned*)(g_gh + (size_t)R0 * 64 + k0);
            ag[1] = *(const unsigned*)(g_gh + (size_t)R1 * 64 + k0);
            ag[2] = *(const unsigned*)(g_gh + (size_t)R0 * 64 + k0 + 8);
            ag[3] = *(const unsigned*)(g_gh + (size_t)R1 * 64 + k0 + 8);
            ax[0] = *(const unsigned*)(g_xh + (size_t)R0 * 64 + k0);
            ax[1] = *(const unsigned*)(g_xh + (size_t)R1 * 64 + k0);
            ax[2] = *(const unsigned*)(g_xh + (size_t)R0 * 64 + k0 + 8);
            ax[3] = *(const unsigned*)(g_xh + (size_t)R1 * 64 + k0 + 8);
#pragma unroll
            for (int q = 0; q < 4; q++) {
                __half2 hp = __hmul2(h2u(ag[q]), h2u(ax[q]));
                ap[q] = *reinterpret_cast<unsigned*>(&hp);
            }
#pragma unroll
            for (int j = 0; j < 8; j++) {
                const __half* wpg = &sWg[(8 * j + qr) * WPITCH + 16 * t + qc];
                const __half* wpb = &sWb[(8 * j + qr) * WPITCH + 16 * t + qc];
                unsigned bg[2], bb[2];
                bg[0] = *(const unsigned*)(wpg);
                bg[1] = *(const unsigned*)(wpg + 8);
                bb[0] = *(const unsigned*)(wpb);
                bb[1] = *(const unsigned*)(wpb + 8);
                mma16816(cg[j], ag, bg);
                mma16816(cp[j], ap, bb);
            }
        }
        // epilogue: y = lrelu(gc + bgc + x) + lrelu(bi + bbi); row-normalize; mean-acc
        float ssA = 0.f, ssB = 0.f;
#pragma unroll
        for (int j = 0; j < 8; j++) {
            int d0 = 8 * j + qc;
            float2 xA = __half22float2(*(const __half2*)(g_xh + (size_t)R0 * 64 + d0));
            float2 xB = __half22float2(*(const __half2*)(g_xh + (size_t)R1 * 64 + d0));
            float bg0 = sbg[d0], bg1 = sbg[d0 + 1];
            float bb0 = sbb[d0], bb1 = sbb[d0 + 1];
            float yA0 = lrelu(cg[j][0] + bg0 + xA.x) + lrelu(cp[j][0] + bb0);
            float yA1 = lrelu(cg[j][1] + bg1 + xA.y) + lrelu(cp[j][1] + bb1);
            float yB0 = lrelu(cg[j][2] + bg0 + xB.x) + lrelu(cp[j][2] + bb0);
            float yB1 = lrelu(cg[j][3] + bg1 + xB.y) + lrelu(cp[j][3] + bb1);
            cg[j][0] = yA0; cg[j][1] = yA1; cg[j][2] = yB0; cg[j][3] = yB1;
            // stash x in the now-dead cp fragments (used when first==1: acc==x)
            cp[j][0] = xA.x; cp[j][1] = xA.y; cp[j][2] = xB.x; cp[j][3] = xB.y;
            ssA += yA0 * yA0 + yA1 * yA1;
            ssB += yB0 * yB0 + yB1 * yB1;
        }
        ssA += __shfl_xor_sync(0xffffffffu, ssA, 1);
        ssA += __shfl_xor_sync(0xffffffffu, ssA, 2);
        ssB += __shfl_xor_sync(0xffffffffu, ssB, 1);
        ssB += __shfl_xor_sync(0xffffffffu, ssB, 2);
        float scA = 1.0f / fmaxf(sqrtf(ssA), 1e-12f);
        float scB = 1.0f / fmaxf(sqrtf(ssB), 1e-12f);
        float sA = 0.f, sB = 0.f;
        if (!last) {
            sA = (R0 < NUQ) ? g_su[R0] : g_si[R0 - NUQ];
            sB = (R1 < NUQ) ? g_su[R1] : g_si[R1 - NUQ];
        }
#pragma unroll
        for (int j = 0; j < 8; j++) {
            int d0 = 8 * j + qc;
            float yA0 = cg[j][0] * scA, yA1 = cg[j][1] * scA;
            float yB0 = cg[j][2] * scB, yB1 = cg[j][3] * scB;
            float2 aA, aB;
            if (first) {
                aA = make_float2(cp[j][0], cp[j][1]);
                aB = make_float2(cp[j][2], cp[j][3]);
            } else {
                aA = __half22float2(*(const __half2*)(g_acc + (size_t)R0 * 64 + d0));
                aB = __half22float2(*(const __half2*)(g_acc + (size_t)R1 * 64 + d0));
            }
            if (last) {
                *(float2*)(out + (size_t)R0 * 64 + d0) =
                    make_float2((aA.x + yA0) * 0.25f, (aA.y + yA1) * 0.25f);
                *(float2*)(out + (size_t)R1 * 64 + d0) =
                    make_float2((aB.x + yB0) * 0.25f, (aB.y + yB1) * 0.25f);
            } else {
                *(__half2*)(g_xh + (size_t)R0 * 64 + d0) = __floats2half2_rn(yA0, yA1);
                *(__half2*)(g_xh + (size_t)R1 * 64 + d0) = __floats2half2_rn(yB0, yB1);
                *(__half2*)(g_acc + (size_t)R0 * 64 + d0) = __floats2half2_rn(aA.x + yA0, aA.y + yA1);
                *(__half2*)(g_acc + (size_t)R1 * 64 + d0) = __floats2half2_rn(aB.x + yB0, aB.y + yB1);
                *(__half2*)(g_scaled_h + (size_t)R0 * 64 + d0) = __floats2half2_rn(yA0 * sA, yA1 * sA);
                *(__half2*)(g_scaled_h + (size_t)R1 * 64 + d0) = __floats2half2_rn(yB0 * sB, yB1 * sB);
            }
        }
    }
}

// ---------------- launch ----------------
extern "C" void kernel_launch(void* const* d_in, const int* in_sizes, int n_in,
                              void* d_out, int out_size) {
    const float* ue  = (const float*)d_in[0];
    const float* ie  = (const float*)d_in[1];
    const float* Wgc = (const float*)d_in[2];
    const float* bgc = (const float*)d_in[3];
    const float* Wbi = (const float*)d_in[4];
    const float* bbi = (const float*)d_in[5];
    const int*   eu  = (const int*)d_in[6];
    const int*   ei  = (const int*)d_in[7];
    float* out = (float*)d_out;

    const int stage_blocks = (NTOT / 4 + 7) / 8;     // 4 rows/warp, 8 warps/block
    const int epi_blocks = (NTOT / 16 + 15) / 16;    // 4 tiles per warp, 4 warps/block
    const int row_blocks = (NTOT + 255) / 256;

    k_zero<<<256, 256>>>(Wgc, Wbi);
    k_fill<<<(NEQ + 255) / 256, 256>>>(eu, ei);
    k_hist<<<row_blocks, 256>>>();
    k_hscan<<<1, 128>>>();
    k_scatter<<<row_blocks, 256>>>();
    k_init<<<4096, 256>>>(ue, ie);

    static __half* whg_dev = nullptr;
    static __half* whb_dev = nullptr;
    if (!whg_dev) {
        cudaGetSymbolAddress((void**)&whg_dev, g_Whg);
        cudaGetSymbolAddress((void**)&whb_dev, g_Whb);
    }

    for (int l = 0; l < 3; l++) {
        k_stage1<<<stage_blocks, 256>>>();
        k_stage2<<<stage_blocks, 256>>>();
        k_epi<<<epi_blocks, 128>>>(whg_dev + l * 4096, bgc + l * 64,
                                   whb_dev + l * 4096, bbi + l * 64,
                                   out, l == 0 ? 1 : 0, l == 2 ? 1 : 0);
    }
}